// round 6
// baseline (speedup 1.0000x reference)
#include <cuda_runtime.h>
#include <cuda_bf16.h>

#define Hd 256
#define Wd 256
#define HWn 65536
#define Bn 4
#define Dn 5
#define Cn 3
#define Sn 27

#define RES_OFF  0L
#define OUT_OFF  (4L*3*3*HWn)
#define SAMP_OFF (OUT_OFF + 4L*3*HWn)

typedef unsigned short u16;
typedef unsigned int u32;

// ---------------- bf16 hi/lo scratch planes ----------------
__device__ u16 g_data_h[4L*15*HWn],  g_data_l[4L*15*HWn];
__device__ u16 g_f1_h[4L*64*HWn],    g_f1_l[4L*64*HWn];
__device__ u16 g_feat_h[4L*128*HWn], g_feat_l[4L*128*HWn];
__device__ u16 g_samp_h[4L*81*HWn],  g_samp_l[4L*81*HWn];
__device__ u16 g_h1_h[4L*64*HWn],    g_h1_l[4L*64*HWn];
__device__ u16 g_h2_h[4L*64*HWn],    g_h2_l[4L*64*HWn];
__device__ float g_off[4L*81*HWn];
__device__ float g_wt[4L*27*HWn];
// B in register-fragment order: per conv up to 32768 uint4
__device__ uint4 g_bfrag[6L*32768];

__device__ __forceinline__ u16 bf16_hi(float v) {
    __nv_bfloat16 h = __float2bfloat16(v);
    return *reinterpret_cast<u16*>(&h);
}
__device__ __forceinline__ float bf16_f(u16 b) {
    __nv_bfloat16 h = *reinterpret_cast<__nv_bfloat16*>(&b);
    return __bfloat162float(h);
}

// ---------------------------------------------------------------------------
__global__ void split_k(const float* __restrict__ src, u16* __restrict__ dh,
                        u16* __restrict__ dl, long n)
{
    long i = blockIdx.x * 256L + threadIdx.x;
    if (i >= n) return;
    float v = src[i];
    u16 h = bf16_hi(v);
    dh[i] = h;
    dl[i] = bf16_hi(v - bf16_f(h));
}

// ---------------------------------------------------------------------------
// pack weights straight into mma B-fragment order.
// Element e = ((q)*NT + nt)*32 + lane, q = kc*4+ks (16-k step index).
// lane: g=lane>>2 (n within 8), t=lane&3. b0={B[n][kb],B[n][kb+1]},
// b1={B[n][kb+8],B[n][kb+9]}, kb = q*16+2t. uint4 = {bh0,bh1,bl0,bl1}.
// ---------------------------------------------------------------------------
__global__ void packwf_k(const float* __restrict__ w, uint4* __restrict__ dst,
                         int COUT, int K, int Kpad, int NT)
{
    long total = (long)(Kpad >> 4) * NT * 32;
    long e = blockIdx.x * 256L + threadIdx.x;
    if (e >= total) return;
    int lane = (int)(e & 31);
    long r = e >> 5;
    int nt = (int)(r % NT);
    int q  = (int)(r / NT);
    int g = lane >> 2, t = lane & 3;
    int n = nt * 8 + g;
    int kb = q * 16 + 2 * t;

    float v[4];
    int kk[4] = {kb, kb + 1, kb + 8, kb + 9};
#pragma unroll
    for (int i = 0; i < 4; i++)
        v[i] = (n < COUT && kk[i] < K) ? w[(long)n * K + kk[i]] : 0.f;

    u16 h[4], l[4];
#pragma unroll
    for (int i = 0; i < 4; i++) {
        h[i] = bf16_hi(v[i]);
        l[i] = bf16_hi(v[i] - bf16_f(h[i]));
    }
    uint4 o;
    o.x = (u32)h[0] | ((u32)h[1] << 16);   // bh0
    o.y = (u32)h[2] | ((u32)h[3] << 16);   // bh1
    o.z = (u32)l[0] | ((u32)l[1] << 16);   // bl0
    o.w = (u32)l[2] | ((u32)l[3] << 16);   // bl1
    dst[e] = o;
}

// ---------------------------------------------------------------------------
__device__ __forceinline__ void mma16816(float d[4], const u32 a[4], u32 b0, u32 b1)
{
    asm volatile(
        "mma.sync.aligned.m16n8k16.row.col.f32.bf16.bf16.f32 "
        "{%0,%1,%2,%3}, {%4,%5,%6,%7}, {%8,%9}, {%0,%1,%2,%3};"
        : "+f"(d[0]), "+f"(d[1]), "+f"(d[2]), "+f"(d[3])
        : "r"(a[0]), "r"(a[1]), "r"(a[2]), "r"(a[3]), "r"(b0), "r"(b1));
}

// ---------------------------------------------------------------------------
// Implicit-GEMM 3x3 conv. A in SMEM k-pair interleaved:
//   Apair[kp][m] (u32) = {A[m][2kp] , A[m][2kp+1]}, pitch 136 u32 (bank-shift 8
//   -> lane pattern 8t+g covers all 32 banks, conflict-free LDS.32).
// B fragments straight from gmem (uint4 per (ks,nt,lane), coalesced, L1-hot).
// ---------------------------------------------------------------------------
#define APITCH 136
template<int NT>
__global__ void __launch_bounds__(256)
convM_k(const u16* __restrict__ s0h, const u16* __restrict__ s0l, int c0,
        const u16* __restrict__ s1h, const u16* __restrict__ s1l, int c1,
        const u16* __restrict__ s2h, const u16* __restrict__ s2l,
        const uint4* __restrict__ bfrag,
        const float* __restrict__ bias,
        u16* __restrict__ dsth, u16* __restrict__ dstl, float* __restrict__ dstf,
        int CIN, int COUT, int Kpad, int relu)
{
    extern __shared__ char sm[];
    u32* Ah = (u32*)sm;                          // 32 rows x 136 u32
    u32* Al = (u32*)(sm + 32 * APITCH * 4);

    const int tid = threadIdx.x;
    const int wid = tid >> 5;
    const int lane = tid & 31;
    const int g = lane >> 2;
    const int t = lane & 3;
    const int bidx = blockIdx.x;
    const int b = bidx >> 9;
    const int pix = (bidx & 511) * 128;
    const int h = pix >> 8;
    const int w0 = pix & 255;
    const int mb = wid * 16;

    float acc[NT][4];
#pragma unroll
    for (int i = 0; i < NT; i++)
#pragma unroll
        for (int j = 0; j < 4; j++) acc[i][j] = 0.f;

    const int K_eff = CIN * 9;
    const int c01 = c0 + c1;
    const int c2 = CIN - c01;
    const int nchunk = Kpad >> 6;

    for (int kc = 0; kc < nchunk; ++kc) {
        __syncthreads();   // previous chunk's fragment reads complete

        // ---- A tile: im2col into k-pair interleaved layout ----
        for (int e = tid; e < 512; e += 256) {
            int kp = e >> 4;               // 0..31
            int mg = (e & 15) * 8;         // m group base
            u32 wh[8], wl[8];
#pragma unroll
            for (int j = 0; j < 8; j++) { wh[j] = 0u; wl[j] = 0u; }
#pragma unroll
            for (int sub = 0; sub < 2; sub++) {
                int k = kc * 64 + kp * 2 + sub;
                if (k >= K_eff) continue;
                int cin = k / 9;
                int tap = k - cin * 9;
                int hh = h + tap / 3 - 1;
                if ((unsigned)hh >= 256u) continue;
                const u16 *ph, *pl;
                if (cin < c0)       { ph = s0h + ((long)b * c0 + cin) * HWn;
                                      pl = s0l + ((long)b * c0 + cin) * HWn; }
                else if (cin < c01) { ph = s1h + ((long)b * c1 + cin - c0) * HWn;
                                      pl = s1l + ((long)b * c1 + cin - c0) * HWn; }
                else                { int cc = cin - c01;
                                      ph = s2h + ((long)b * c2 + cc) * HWn;
                                      pl = s2l + ((long)b * c2 + cc) * HWn; }
                long rowo = (long)hh * 256;
                int wwb = w0 + mg + (tap % 3) - 1;
                int sh = 16 * sub;
#pragma unroll
                for (int j = 0; j < 8; j++) {
                    int ww = wwb + j;
                    if ((unsigned)ww < 256u) {
                        wh[j] |= (u32)ph[rowo + ww] << sh;
                        wl[j] |= (u32)pl[rowo + ww] << sh;
                    }
                }
            }
            u32* dh_ = Ah + kp * APITCH + mg;
            u32* dl_ = Al + kp * APITCH + mg;
            *(uint4*)(dh_)     = make_uint4(wh[0], wh[1], wh[2], wh[3]);
            *(uint4*)(dh_ + 4) = make_uint4(wh[4], wh[5], wh[6], wh[7]);
            *(uint4*)(dl_)     = make_uint4(wl[0], wl[1], wl[2], wl[3]);
            *(uint4*)(dl_ + 4) = make_uint4(wl[4], wl[5], wl[6], wl[7]);
        }
        __syncthreads();

        // ---- MMA: 4 k-steps of 16 ----
#pragma unroll
        for (int ks = 0; ks < 4; ks++) {
            const int kp0 = ks * 8 + t;
            const int m = mb + g;
            u32 ah[4], al[4];
            ah[0] = Ah[kp0 * APITCH + m];
            ah[1] = Ah[kp0 * APITCH + m + 8];
            ah[2] = Ah[(kp0 + 4) * APITCH + m];
            ah[3] = Ah[(kp0 + 4) * APITCH + m + 8];
            al[0] = Al[kp0 * APITCH + m];
            al[1] = Al[kp0 * APITCH + m + 8];
            al[2] = Al[(kp0 + 4) * APITCH + m];
            al[3] = Al[(kp0 + 4) * APITCH + m + 8];

            const uint4* bp = bfrag + ((long)(kc * 4 + ks) * NT) * 32 + lane;
#pragma unroll
            for (int nt = 0; nt < NT; nt++) {
                uint4 bv = bp[nt * 32];
                mma16816(acc[nt], ah, bv.x, bv.y);   // Ah*Bh
                mma16816(acc[nt], al, bv.x, bv.y);   // Al*Bh
                mma16816(acc[nt], ah, bv.z, bv.w);   // Ah*Bl
            }
        }
    }

    // ---- epilogue ----
#pragma unroll
    for (int nt = 0; nt < NT; nt++) {
        int n0 = nt * 8 + t * 2;
#pragma unroll
        for (int i = 0; i < 4; i++) {
            int n = n0 + (i & 1);
            if (n >= COUT) continue;
            int m = mb + g + ((i & 2) ? 8 : 0);
            float v = acc[nt][i] + bias[n];
            if (relu) v = fmaxf(v, 0.f);
            long o = ((long)b * COUT + n) * HWn + pix + m;
            if (dsth) {
                u16 hv = bf16_hi(v);
                dsth[o] = hv;
                dstl[o] = bf16_hi(v - bf16_f(hv));
            }
            if (dstf) dstf[o] = v;
        }
    }
}

// ---------------------------------------------------------------------------
__global__ void trilerp_k(const float* __restrict__ data,
                          const float* __restrict__ off,
                          float* __restrict__ samp,
                          u16* __restrict__ sh, u16* __restrict__ sl)
{
    long idx = blockIdx.x * 256L + threadIdx.x;
    if (idx >= (long)Bn * Sn * HWn) return;
    int hw = (int)(idx % HWn);
    int s  = (int)((idx / HWn) % Sn);
    int b  = (int)(idx / ((long)Sn * HWn));
    int h = hw >> 8, w = hw & 255;

    int kd = s / 9 - 1, kh = (s / 3) % 3 - 1, kw = s % 3 - 1;

    const float* ob = off + ((long)b * (Sn * 3) + s * 3) * HWn + hw;
    float pd = 2.0f + (float)kd + ob[0];
    float ph = (float)h + (float)kh + ob[HWn];
    float pw = (float)w + (float)kw + ob[2L * HWn];
    pd = fminf(fmaxf(pd, 0.f), (float)(Dn - 1));
    ph = fminf(fmaxf(ph, 0.f), (float)(Hd - 1));
    pw = fminf(fmaxf(pw, 0.f), (float)(Wd - 1));

    float d0f = floorf(pd), h0f = floorf(ph), w0f = floorf(pw);
    float fd = pd - d0f, fh = ph - h0f, fw = pw - w0f;
    int d0 = (int)d0f, h0 = (int)h0f, w0 = (int)w0f;
    int d1 = min(d0 + 1, Dn - 1), h1 = min(h0 + 1, Hd - 1), w1 = min(w0 + 1, Wd - 1);

    float gd0 = 1.f - fd, gh0 = 1.f - fh, gw0 = 1.f - fw;
    float w000 = gd0*gh0*gw0, w001 = gd0*gh0*fw, w010 = gd0*fh*gw0, w011 = gd0*fh*fw;
    float w100 = fd*gh0*gw0,  w101 = fd*gh0*fw,  w110 = fd*fh*gw0,  w111 = fd*fh*fw;

    long i00 = (long)h0 * Wd + w0, i01 = (long)h0 * Wd + w1;
    long i10 = (long)h1 * Wd + w0, i11 = (long)h1 * Wd + w1;

#pragma unroll
    for (int c = 0; c < Cn; c++) {
        const float* p0 = data + (((long)b * Dn + d0) * Cn + c) * HWn;
        const float* p1 = data + (((long)b * Dn + d1) * Cn + c) * HWn;
        float v = w000*p0[i00] + w001*p0[i01] + w010*p0[i10] + w011*p0[i11]
                + w100*p1[i00] + w101*p1[i01] + w110*p1[i10] + w111*p1[i11];
        long o = (((long)b * Sn + s) * Cn + c) * HWn + hw;
        samp[o] = v;
        u16 hv = bf16_hi(v);
        sh[o] = hv;
        sl[o] = bf16_hi(v - bf16_f(hv));
    }
}

// ---------------------------------------------------------------------------
__global__ void combine_k(const float* __restrict__ samp,
                          const float* __restrict__ wts,
                          float* __restrict__ res_i, float* __restrict__ outp)
{
    long idx = blockIdx.x * 256L + threadIdx.x;
    if (idx >= (long)Bn * HWn) return;
    int hw = (int)(idx % HWn);
    int b  = (int)(idx / HWn);

    float wv[Sn];
#pragma unroll
    for (int s = 0; s < Sn; s++) wv[s] = wts[((long)b * Sn + s) * HWn + hw];

    float o[3] = {0.f, 0.f, 0.f};
#pragma unroll
    for (int g = 0; g < 3; g++) {
#pragma unroll
        for (int c = 0; c < 3; c++) {
            float r = 0.f;
#pragma unroll
            for (int k = 0; k < 9; k++) {
                int s = g * 9 + k;
                r += samp[(((long)b * Sn + s) * Cn + c) * HWn + hw] * wv[s];
            }
            r *= 3.0f;
            res_i[(((long)b * 3 + g) * 3 + c) * HWn + hw] = r;
            o[c] += r;
        }
    }
#pragma unroll
    for (int c = 0; c < 3; c++)
        outp[((long)b * 3 + c) * HWn + hw] = o[c] * (1.0f / 3.0f);
}

// ---------------------------------------------------------------------------
extern "C" void kernel_launch(void* const* d_in, const int* in_sizes, int n_in,
                              void* d_out, int out_size)
{
    const float* data   = (const float*)d_in[0];
    const float* enc_w1 = (const float*)d_in[1];
    const float* enc_b1 = (const float*)d_in[2];
    const float* enc_w2 = (const float*)d_in[3];
    const float* enc_b2 = (const float*)d_in[4];
    const float* off_w  = (const float*)d_in[5];
    const float* off_b  = (const float*)d_in[6];
    const float* wc_w1  = (const float*)d_in[7];
    const float* wc_b1  = (const float*)d_in[8];
    const float* wc_w2  = (const float*)d_in[9];
    const float* wc_b2  = (const float*)d_in[10];
    const float* wc_w3  = (const float*)d_in[11];
    const float* wc_b3  = (const float*)d_in[12];
    float* out = (float*)d_out;

    u16 *dh, *dl, *f1h, *f1l, *fth, *ftl, *sph, *spl, *h1h, *h1l, *h2h, *h2l;
    float *offs, *wt;
    uint4* bf;
    cudaGetSymbolAddress((void**)&dh,  g_data_h);  cudaGetSymbolAddress((void**)&dl,  g_data_l);
    cudaGetSymbolAddress((void**)&f1h, g_f1_h);    cudaGetSymbolAddress((void**)&f1l, g_f1_l);
    cudaGetSymbolAddress((void**)&fth, g_feat_h);  cudaGetSymbolAddress((void**)&ftl, g_feat_l);
    cudaGetSymbolAddress((void**)&sph, g_samp_h);  cudaGetSymbolAddress((void**)&spl, g_samp_l);
    cudaGetSymbolAddress((void**)&h1h, g_h1_h);    cudaGetSymbolAddress((void**)&h1l, g_h1_l);
    cudaGetSymbolAddress((void**)&h2h, g_h2_h);    cudaGetSymbolAddress((void**)&h2l, g_h2_l);
    cudaGetSymbolAddress((void**)&offs, g_off);    cudaGetSymbolAddress((void**)&wt,  g_wt);
    cudaGetSymbolAddress((void**)&bf,  g_bfrag);

    float* res_i = out + RES_OFF;
    float* outp  = out + OUT_OFF;
    float* samp  = out + SAMP_OFF;

    // conv table: {w, b, CIN, COUT, Kpad, Npad}
    struct CV { const float* w; const float* bs; int CIN, COUT, Kpad, Npad; };
    CV cv[6] = {
        {enc_w1, enc_b1,  15,  64,  192,  64},
        {enc_w2, enc_b2,  64, 128,  576, 128},
        {off_w,  off_b,  128,  81, 1152,  96},
        {wc_w1,  wc_b1,  224,  64, 2048,  64},
        {wc_w2,  wc_b2,   64,  64,  576,  64},
        {wc_w3,  wc_b3,   64,  27,  576,  32},
    };

    // 0) split input to bf16 hi/lo
    {
        long n = 4L * 15 * HWn;
        split_k<<<(unsigned)((n + 255) / 256), 256>>>(data, dh, dl, n);
    }
    // pack weights into fragment order
    for (int i = 0; i < 6; i++) {
        int NT = cv[i].Npad / 8;
        long n = (long)(cv[i].Kpad >> 4) * NT * 32;
        packwf_k<<<(unsigned)((n + 255) / 256), 256>>>(cv[i].w, bf + i * 32768L,
                                                       cv[i].COUT, cv[i].CIN * 9,
                                                       cv[i].Kpad, NT);
    }

    const unsigned GRID = 2048;
    const size_t DSM = 2 * 32 * APITCH * 4;   // 34816 B

    auto launch = [&](int ci, const u16* a0h, const u16* a0l, int c0,
                      const u16* a1h, const u16* a1l, int c1,
                      const u16* a2h, const u16* a2l,
                      u16* oh, u16* ol, float* of, int relu) {
        const CV& c = cv[ci];
        const uint4* wb = bf + ci * 32768L;
        switch (c.Npad / 8) {
        case 4:  convM_k<4><<<GRID, 256, DSM>>>(a0h, a0l, c0, a1h, a1l, c1, a2h, a2l,
                    wb, c.bs, oh, ol, of, c.CIN, c.COUT, c.Kpad, relu); break;
        case 8:  convM_k<8><<<GRID, 256, DSM>>>(a0h, a0l, c0, a1h, a1l, c1, a2h, a2l,
                    wb, c.bs, oh, ol, of, c.CIN, c.COUT, c.Kpad, relu); break;
        case 12: convM_k<12><<<GRID, 256, DSM>>>(a0h, a0l, c0, a1h, a1l, c1, a2h, a2l,
                    wb, c.bs, oh, ol, of, c.CIN, c.COUT, c.Kpad, relu); break;
        default: convM_k<16><<<GRID, 256, DSM>>>(a0h, a0l, c0, a1h, a1l, c1, a2h, a2l,
                    wb, c.bs, oh, ol, of, c.CIN, c.COUT, c.Kpad, relu); break;
        }
    };

    // 1) f1 = relu(conv(data 15->64))
    launch(0, dh, dl, 15, nullptr, nullptr, 0, nullptr, nullptr, f1h, f1l, nullptr, 1);
    // 2) feature = relu(conv(f1 64->128))
    launch(1, f1h, f1l, 64, nullptr, nullptr, 0, nullptr, nullptr, fth, ftl, nullptr, 1);
    // 3) offsets = conv(feature 128->81), fp32
    launch(2, fth, ftl, 128, nullptr, nullptr, 0, nullptr, nullptr, nullptr, nullptr, offs, 0);
    // 4) samples
    {
        long n = (long)Bn * Sn * HWn;
        trilerp_k<<<(unsigned)((n + 255) / 256), 256>>>(data, offs, samp, sph, spl);
    }
    // 5) h1 = relu(conv(concat(data15, feat128, samp81) 224->64))
    launch(3, dh, dl, 15, fth, ftl, 128, sph, spl, h1h, h1l, nullptr, 1);
    // 6) h2 = relu(conv(h1 64->64))
    launch(4, h1h, h1l, 64, nullptr, nullptr, 0, nullptr, nullptr, h2h, h2l, nullptr, 1);
    // 7) weights = conv(h2 64->27), fp32
    launch(5, h2h, h2l, 64, nullptr, nullptr, 0, nullptr, nullptr, nullptr, nullptr, wt, 0);
    // 8) combine
    {
        long n = (long)Bn * HWn;
        combine_k<<<(unsigned)((n + 255) / 256), 256>>>(samp, wt, res_i, outp);
    }
}

// round 7
// speedup vs baseline: 1.2824x; 1.2824x over previous
#include <cuda_runtime.h>
#include <cuda_bf16.h>

#define Hd 256
#define Wd 256
#define HWn 65536
#define Bn 4
#define Dn 5
#define Cn 3
#define Sn 27

#define RES_OFF  0L
#define OUT_OFF  (4L*3*3*HWn)
#define SAMP_OFF (OUT_OFF + 4L*3*HWn)

typedef unsigned short u16;
typedef unsigned int u32;

#define GUARD 16   // u16 guard elements before/after each plane region

// ---------------- bf16 hi/lo scratch planes (guarded, 16B aligned) --------
__device__ __align__(16) u16 g_data_h[4L*15*HWn + 2*GUARD],  g_data_l[4L*15*HWn + 2*GUARD];
__device__ __align__(16) u16 g_f1_h[4L*64*HWn + 2*GUARD],    g_f1_l[4L*64*HWn + 2*GUARD];
__device__ __align__(16) u16 g_feat_h[4L*128*HWn + 2*GUARD], g_feat_l[4L*128*HWn + 2*GUARD];
__device__ __align__(16) u16 g_samp_h[4L*81*HWn + 2*GUARD],  g_samp_l[4L*81*HWn + 2*GUARD];
__device__ __align__(16) u16 g_h1_h[4L*64*HWn + 2*GUARD],    g_h1_l[4L*64*HWn + 2*GUARD];
__device__ __align__(16) u16 g_h2_h[4L*64*HWn + 2*GUARD],    g_h2_l[4L*64*HWn + 2*GUARD];
__device__ float g_off[4L*81*HWn];
__device__ float g_wt[4L*27*HWn];
__device__ uint4 g_bfrag[6L*40960];   // fragment-ordered weights per conv

__device__ __forceinline__ u16 bf16_hi(float v) {
    __nv_bfloat16 h = __float2bfloat16(v);
    return *reinterpret_cast<u16*>(&h);
}
__device__ __forceinline__ float bf16_f(u16 b) {
    __nv_bfloat16 h = *reinterpret_cast<__nv_bfloat16*>(&b);
    return __bfloat162float(h);
}
__device__ __forceinline__ u32 smem_u32(const void* p) {
    u32 a;
    asm("{ .reg .u64 t; cvta.to.shared.u64 t, %1; cvt.u32.u64 %0, t; }" : "=r"(a) : "l"(p));
    return a;
}
__device__ __forceinline__ void cp16(u32 dst, const void* src) {
    asm volatile("cp.async.cg.shared.global [%0], [%1], 16;" :: "r"(dst), "l"(src));
}
#define CP_COMMIT() asm volatile("cp.async.commit_group;")

// ---------------------------------------------------------------------------
__global__ void split_k(const float* __restrict__ src, u16* __restrict__ dh,
                        u16* __restrict__ dl, long n)
{
    long i = blockIdx.x * 256L + threadIdx.x;
    if (i >= n) return;
    float v = src[i];
    u16 h = bf16_hi(v);
    dh[i] = h;
    dl[i] = bf16_hi(v - bf16_f(h));
}

// ---------------------------------------------------------------------------
// pack weights into mma B-fragment order (verified in round 6):
// element e = (q*NTt + ng)*32 + lane, q = 16-k step; lane g=lane>>2, t=lane&3;
// n = ng*8+g; kb = q*16+2t; uint4 = {bh0,bh1,bl0,bl1} with pairs (kb,kb+1),(kb+8,kb+9)
// ---------------------------------------------------------------------------
__global__ void packwf_k(const float* __restrict__ w, uint4* __restrict__ dst,
                         int COUT, int K, int Kpad, int NTt)
{
    long total = (long)(Kpad >> 4) * NTt * 32;
    long e = blockIdx.x * 256L + threadIdx.x;
    if (e >= total) return;
    int lane = (int)(e & 31);
    long r = e >> 5;
    int ng = (int)(r % NTt);
    int q  = (int)(r / NTt);
    int g = lane >> 2, t = lane & 3;
    int n = ng * 8 + g;
    int kb = q * 16 + 2 * t;

    float v[4];
    int kk[4] = {kb, kb + 1, kb + 8, kb + 9};
#pragma unroll
    for (int i = 0; i < 4; i++)
        v[i] = (n < COUT && kk[i] < K) ? w[(long)n * K + kk[i]] : 0.f;

    u16 h[4], l[4];
#pragma unroll
    for (int i = 0; i < 4; i++) {
        h[i] = bf16_hi(v[i]);
        l[i] = bf16_hi(v[i] - bf16_f(h[i]));
    }
    uint4 o;
    o.x = (u32)h[0] | ((u32)h[1] << 16);
    o.y = (u32)h[2] | ((u32)h[3] << 16);
    o.z = (u32)l[0] | ((u32)l[1] << 16);
    o.w = (u32)l[2] | ((u32)l[3] << 16);
    dst[e] = o;
}

// ---------------------------------------------------------------------------
__device__ __forceinline__ void mma16816(float d[4], const u32 a[4], u32 b0, u32 b1)
{
    asm volatile(
        "mma.sync.aligned.m16n8k16.row.col.f32.bf16.bf16.f32 "
        "{%0,%1,%2,%3}, {%4,%5,%6,%7}, {%8,%9}, {%0,%1,%2,%3};"
        : "+f"(d[0]), "+f"(d[1]), "+f"(d[2]), "+f"(d[3])
        : "r"(a[0]), "r"(a[1]), "r"(a[2]), "r"(a[3]), "r"(b0), "r"(b1));
}

// ---------------------------------------------------------------------------
// Implicit-GEMM 3x3 conv, M=256 (one full image row), N=64 slice per block.
// A: raw input rows (cin,kh) with +-8 halo in SMEM; shift applied at
// fragment load: At[k][m] = Raw[tt(k)][m + kw(k) + 7].
// B: fragment-ordered uint4 staged in SMEM. cp.async double-buffered.
// ---------------------------------------------------------------------------
#define A_ROWS  22
#define A_PITCH 272                         // u16 per raw row
#define A_PLANE (A_ROWS*A_PITCH)            // u16 per plane
#define A_BUFB  (2*A_PLANE*2)               // bytes per A buffer (hi+lo)

template<int NT>
__global__ void __launch_bounds__(256)
convM_k(const u16* __restrict__ s0h, const u16* __restrict__ s0l, int c0,
        const u16* __restrict__ s1h, const u16* __restrict__ s1l, int c1,
        const u16* __restrict__ s2h, const u16* __restrict__ s2l,
        const uint4* __restrict__ bfrag,
        const float* __restrict__ bias,
        u16* __restrict__ dsth, u16* __restrict__ dstl, float* __restrict__ dstf,
        int CIN, int COUT, int Kpad, int NTt, int relu)
{
    extern __shared__ char sm[];
    const u32 smbase = smem_u32(sm);
    const int BSZB = 128 * NT * 16;          // bytes per B buffer

    const int tid = threadIdx.x;
    const int wid = tid >> 5;
    const int lane = tid & 31;
    const int g = lane >> 2;
    const int t = lane & 3;
    const int b = blockIdx.x >> 8;
    const int h = blockIdx.x & 255;
    const int slice = blockIdx.y;
    const int mb = wid * 16;

    const int c01 = c0 + c1;
    const int c2 = CIN - c01;
    const int nchunk = Kpad >> 6;

    float acc[2][NT][4];
#pragma unroll
    for (int mt = 0; mt < 2; mt++)
#pragma unroll
        for (int i = 0; i < NT; i++)
#pragma unroll
            for (int j = 0; j < 4; j++) acc[mt][i][j] = 0.f;

    // ---- fill one chunk's A raw rows + B fragments into buffer `buf` ----
    auto fill = [&](int kc, int buf) {
        const int K0 = kc * 64;
        const int T0 = (K0 * 21846) >> 16;
        const u32 abase = smbase + buf * A_BUFB;
        // A: 22 rows x 34 16B-chunks x 2 planes
        for (int e = tid; e < A_ROWS * 34 * 2; e += 256) {
            int tt = e / 68;
            int r = e - tt * 68;
            int pl = r >= 34;
            int j = r - pl * 34;
            int T = T0 + tt;
            int cin = T / 3;
            int kh = T - cin * 3;
            int hh = h + kh - 1;
            u32 dst = abase + (u32)(pl * A_PLANE + tt * A_PITCH + j * 8) * 2;
            if (cin < CIN && (unsigned)hh < 256u) {
                const u16* sp;
                if (cin < c0)       sp = (pl ? s0l : s0h) + ((long)b * c0 + cin) * HWn;
                else if (cin < c01) sp = (pl ? s1l : s1h) + ((long)b * c1 + (cin - c0)) * HWn;
                else                sp = (pl ? s2l : s2h) + ((long)b * c2 + (cin - c01)) * HWn;
                cp16(dst, sp + (long)hh * 256 + j * 8 - 8);
            } else {
                asm volatile("st.shared.v4.b32 [%0], {%1,%1,%1,%1};" :: "r"(dst), "r"(0u));
            }
        }
        // B: 128*NT uint4 in fragment order
        const u32 bbase = smbase + 2 * A_BUFB + buf * BSZB;
        const int q0 = kc * 4;
        for (int e = tid; e < 128 * NT; e += 256) {
            int ks = e / (NT * 32);
            int r = e - ks * (NT * 32);
            int nt = r >> 5;
            int ln = r & 31;
            const uint4* src = bfrag + ((long)(q0 + ks) * NTt + slice * 8 + nt) * 32 + ln;
            cp16(bbase + (u32)e * 16, src);
        }
    };

    fill(0, 0);
    CP_COMMIT();

    for (int kc = 0; kc < nchunk; ++kc) {
        const int buf = kc & 1;
        if (kc + 1 < nchunk) {
            fill(kc + 1, buf ^ 1);
            CP_COMMIT();
            asm volatile("cp.async.wait_group 1;");
        } else {
            asm volatile("cp.async.wait_group 0;");
        }
        __syncthreads();

        // edge fixups: zero halo cells ww=-1 (idx 7) and ww=256 (idx 264)
        u16* Rh = (u16*)(sm + buf * A_BUFB);
        u16* Rl = Rh + A_PLANE;
        if (tid < A_ROWS) {
            Rh[tid * A_PITCH + 7] = 0;   Rh[tid * A_PITCH + 264] = 0;
            Rl[tid * A_PITCH + 7] = 0;   Rl[tid * A_PITCH + 264] = 0;
        }
        __syncthreads();

        const uint4* Bsm = (const uint4*)(sm + 2 * A_BUFB + buf * BSZB);
        const int K0 = kc * 64;
        const int T0 = (K0 * 21846) >> 16;

#pragma unroll
        for (int ks = 0; ks < 4; ks++) {
            int kg = K0 + ks * 16 + 2 * t;
            int Ta = (kg * 21846) >> 16;        int kwa = kg - Ta * 3;
            int Tb = ((kg + 1) * 21846) >> 16;  int kwb = kg + 1 - Tb * 3;
            int Tc = ((kg + 8) * 21846) >> 16;  int kwc = kg + 8 - Tc * 3;
            int Td = ((kg + 9) * 21846) >> 16;  int kwd = kg + 9 - Td * 3;
            int ra = (Ta - T0) * A_PITCH + kwa + 7;
            int rb = (Tb - T0) * A_PITCH + kwb + 7;
            int rc = (Tc - T0) * A_PITCH + kwc + 7;
            int rd = (Td - T0) * A_PITCH + kwd + 7;

            u32 ah[2][4], al[2][4];
#pragma unroll
            for (int mt = 0; mt < 2; mt++) {
                int m = mb + mt * 128 + g;
                ah[mt][0] = (u32)Rh[ra + m]     | ((u32)Rh[rb + m]     << 16);
                ah[mt][1] = (u32)Rh[ra + m + 8] | ((u32)Rh[rb + m + 8] << 16);
                ah[mt][2] = (u32)Rh[rc + m]     | ((u32)Rh[rd + m]     << 16);
                ah[mt][3] = (u32)Rh[rc + m + 8] | ((u32)Rh[rd + m + 8] << 16);
                al[mt][0] = (u32)Rl[ra + m]     | ((u32)Rl[rb + m]     << 16);
                al[mt][1] = (u32)Rl[ra + m + 8] | ((u32)Rl[rb + m + 8] << 16);
                al[mt][2] = (u32)Rl[rc + m]     | ((u32)Rl[rd + m]     << 16);
                al[mt][3] = (u32)Rl[rc + m + 8] | ((u32)Rl[rd + m + 8] << 16);
            }
            const uint4* Bp = Bsm + ks * NT * 32 + lane;
#pragma unroll
            for (int nt = 0; nt < NT; nt++) {
                uint4 bv = Bp[nt * 32];
                mma16816(acc[0][nt], ah[0], bv.x, bv.y);
                mma16816(acc[0][nt], al[0], bv.x, bv.y);
                mma16816(acc[0][nt], ah[0], bv.z, bv.w);
                mma16816(acc[1][nt], ah[1], bv.x, bv.y);
                mma16816(acc[1][nt], al[1], bv.x, bv.y);
                mma16816(acc[1][nt], ah[1], bv.z, bv.w);
            }
        }
        __syncthreads();   // protect buf from next prefetch overwrite
    }

    // ---- epilogue ----
#pragma unroll
    for (int mt = 0; mt < 2; mt++)
#pragma unroll
        for (int nt = 0; nt < NT; nt++) {
            int n0 = slice * 64 + nt * 8 + t * 2;
#pragma unroll
            for (int i = 0; i < 4; i++) {
                int n = n0 + (i & 1);
                if (n >= COUT) continue;
                int m = mb + mt * 128 + g + ((i & 2) ? 8 : 0);
                float v = acc[mt][nt][i] + bias[n];
                if (relu) v = fmaxf(v, 0.f);
                long o = ((long)b * COUT + n) * HWn + (long)h * 256 + m;
                if (dsth) {
                    u16 hv = bf16_hi(v);
                    dsth[o] = hv;
                    dstl[o] = bf16_hi(v - bf16_f(hv));
                }
                if (dstf) dstf[o] = v;
            }
        }
}

// ---------------------------------------------------------------------------
__global__ void trilerp_k(const float* __restrict__ data,
                          const float* __restrict__ off,
                          float* __restrict__ samp,
                          u16* __restrict__ sh, u16* __restrict__ sl)
{
    long idx = blockIdx.x * 256L + threadIdx.x;
    if (idx >= (long)Bn * Sn * HWn) return;
    int hw = (int)(idx % HWn);
    int s  = (int)((idx / HWn) % Sn);
    int b  = (int)(idx / ((long)Sn * HWn));
    int h = hw >> 8, w = hw & 255;

    int kd = s / 9 - 1, kh = (s / 3) % 3 - 1, kw = s % 3 - 1;

    const float* ob = off + ((long)b * (Sn * 3) + s * 3) * HWn + hw;
    float pd = 2.0f + (float)kd + ob[0];
    float ph = (float)h + (float)kh + ob[HWn];
    float pw = (float)w + (float)kw + ob[2L * HWn];
    pd = fminf(fmaxf(pd, 0.f), (float)(Dn - 1));
    ph = fminf(fmaxf(ph, 0.f), (float)(Hd - 1));
    pw = fminf(fmaxf(pw, 0.f), (float)(Wd - 1));

    float d0f = floorf(pd), h0f = floorf(ph), w0f = floorf(pw);
    float fd = pd - d0f, fh = ph - h0f, fw = pw - w0f;
    int d0 = (int)d0f, h0 = (int)h0f, w0 = (int)w0f;
    int d1 = min(d0 + 1, Dn - 1), h1 = min(h0 + 1, Hd - 1), w1 = min(w0 + 1, Wd - 1);

    float gd0 = 1.f - fd, gh0 = 1.f - fh, gw0 = 1.f - fw;
    float w000 = gd0*gh0*gw0, w001 = gd0*gh0*fw, w010 = gd0*fh*gw0, w011 = gd0*fh*fw;
    float w100 = fd*gh0*gw0,  w101 = fd*gh0*fw,  w110 = fd*fh*gw0,  w111 = fd*fh*fw;

    long i00 = (long)h0 * Wd + w0, i01 = (long)h0 * Wd + w1;
    long i10 = (long)h1 * Wd + w0, i11 = (long)h1 * Wd + w1;

#pragma unroll
    for (int c = 0; c < Cn; c++) {
        const float* p0 = data + (((long)b * Dn + d0) * Cn + c) * HWn;
        const float* p1 = data + (((long)b * Dn + d1) * Cn + c) * HWn;
        float v = w000*p0[i00] + w001*p0[i01] + w010*p0[i10] + w011*p0[i11]
                + w100*p1[i00] + w101*p1[i01] + w110*p1[i10] + w111*p1[i11];
        long o = (((long)b * Sn + s) * Cn + c) * HWn + hw;
        samp[o] = v;
        u16 hv = bf16_hi(v);
        sh[o] = hv;
        sl[o] = bf16_hi(v - bf16_f(hv));
    }
}

// ---------------------------------------------------------------------------
__global__ void combine_k(const float* __restrict__ samp,
                          const float* __restrict__ wts,
                          float* __restrict__ res_i, float* __restrict__ outp)
{
    long idx = blockIdx.x * 256L + threadIdx.x;
    if (idx >= (long)Bn * HWn) return;
    int hw = (int)(idx % HWn);
    int b  = (int)(idx / HWn);

    float wv[Sn];
#pragma unroll
    for (int s = 0; s < Sn; s++) wv[s] = wts[((long)b * Sn + s) * HWn + hw];

    float o[3] = {0.f, 0.f, 0.f};
#pragma unroll
    for (int g = 0; g < 3; g++) {
#pragma unroll
        for (int c = 0; c < 3; c++) {
            float r = 0.f;
#pragma unroll
            for (int k = 0; k < 9; k++) {
                int s = g * 9 + k;
                r += samp[(((long)b * Sn + s) * Cn + c) * HWn + hw] * wv[s];
            }
            r *= 3.0f;
            res_i[(((long)b * 3 + g) * 3 + c) * HWn + hw] = r;
            o[c] += r;
        }
    }
#pragma unroll
    for (int c = 0; c < 3; c++)
        outp[((long)b * 3 + c) * HWn + hw] = o[c] * (1.0f / 3.0f);
}

// ---------------------------------------------------------------------------
extern "C" void kernel_launch(void* const* d_in, const int* in_sizes, int n_in,
                              void* d_out, int out_size)
{
    const float* data   = (const float*)d_in[0];
    const float* enc_w1 = (const float*)d_in[1];
    const float* enc_b1 = (const float*)d_in[2];
    const float* enc_w2 = (const float*)d_in[3];
    const float* enc_b2 = (const float*)d_in[4];
    const float* off_w  = (const float*)d_in[5];
    const float* off_b  = (const float*)d_in[6];
    const float* wc_w1  = (const float*)d_in[7];
    const float* wc_b1  = (const float*)d_in[8];
    const float* wc_w2  = (const float*)d_in[9];
    const float* wc_b2  = (const float*)d_in[10];
    const float* wc_w3  = (const float*)d_in[11];
    const float* wc_b3  = (const float*)d_in[12];
    float* out = (float*)d_out;

    u16 *dh, *dl, *f1h, *f1l, *fth, *ftl, *sph, *spl, *h1h, *h1l, *h2h, *h2l;
    float *offs, *wt;
    uint4* bf;
    cudaGetSymbolAddress((void**)&dh,  g_data_h);  cudaGetSymbolAddress((void**)&dl,  g_data_l);
    cudaGetSymbolAddress((void**)&f1h, g_f1_h);    cudaGetSymbolAddress((void**)&f1l, g_f1_l);
    cudaGetSymbolAddress((void**)&fth, g_feat_h);  cudaGetSymbolAddress((void**)&ftl, g_feat_l);
    cudaGetSymbolAddress((void**)&sph, g_samp_h);  cudaGetSymbolAddress((void**)&spl, g_samp_l);
    cudaGetSymbolAddress((void**)&h1h, g_h1_h);    cudaGetSymbolAddress((void**)&h1l, g_h1_l);
    cudaGetSymbolAddress((void**)&h2h, g_h2_h);    cudaGetSymbolAddress((void**)&h2l, g_h2_l);
    cudaGetSymbolAddress((void**)&offs, g_off);    cudaGetSymbolAddress((void**)&wt,  g_wt);
    cudaGetSymbolAddress((void**)&bf,  g_bfrag);
    // guarded bases
    dh += GUARD; dl += GUARD; f1h += GUARD; f1l += GUARD; fth += GUARD; ftl += GUARD;
    sph += GUARD; spl += GUARD; h1h += GUARD; h1l += GUARD; h2h += GUARD; h2l += GUARD;

    float* res_i = out + RES_OFF;
    float* outp  = out + OUT_OFF;
    float* samp  = out + SAMP_OFF;

    // conv table: {w, b, CIN, COUT, Kpad, slices}
    struct CV { const float* w; const float* bs; int CIN, COUT, Kpad, slices; };
    CV cv[6] = {
        {enc_w1, enc_b1,  15,  64,  192, 1},
        {enc_w2, enc_b2,  64, 128,  576, 2},
        {off_w,  off_b,  128,  81, 1152, 2},
        {wc_w1,  wc_b1,  224,  64, 2048, 1},
        {wc_w2,  wc_b2,   64,  64,  576, 1},
        {wc_w3,  wc_b3,   64,  27,  576, 1},
    };
    // NTt per conv (total N tiles of 8): conv6 uses 4 (Npad=32)
    int NTt[6] = {8, 16, 16, 8, 8, 4};

    // 0) split input to bf16 hi/lo
    {
        long n = 4L * 15 * HWn;
        split_k<<<(unsigned)((n + 255) / 256), 256>>>(data, dh, dl, n);
    }
    // pack weights into fragment order
    for (int i = 0; i < 6; i++) {
        long n = (long)(cv[i].Kpad >> 4) * NTt[i] * 32;
        packwf_k<<<(unsigned)((n + 255) / 256), 256>>>(cv[i].w, bf + i * 40960L,
                                                       cv[i].COUT, cv[i].CIN * 9,
                                                       cv[i].Kpad, NTt[i]);
    }

    const int DSM8 = 2 * A_BUFB + 2 * 128 * 8 * 16;   // 47872 + 32768 = 80640
    const int DSM4 = 2 * A_BUFB + 2 * 128 * 4 * 16;   // 47872 + 16384 = 64256
    cudaFuncSetAttribute(convM_k<8>, cudaFuncAttributeMaxDynamicSharedMemorySize, DSM8);
    cudaFuncSetAttribute(convM_k<4>, cudaFuncAttributeMaxDynamicSharedMemorySize, DSM4);

    auto launch = [&](int ci, const u16* a0h, const u16* a0l, int c0,
                      const u16* a1h, const u16* a1l, int c1,
                      const u16* a2h, const u16* a2l,
                      u16* oh, u16* ol, float* of, int relu) {
        const CV& c = cv[ci];
        const uint4* wb = bf + ci * 40960L;
        dim3 grid(1024, c.slices);
        if (NTt[ci] == 4)
            convM_k<4><<<grid, 256, DSM4>>>(a0h, a0l, c0, a1h, a1l, c1, a2h, a2l,
                wb, c.bs, oh, ol, of, c.CIN, c.COUT, c.Kpad, NTt[ci], relu);
        else
            convM_k<8><<<grid, 256, DSM8>>>(a0h, a0l, c0, a1h, a1l, c1, a2h, a2l,
                wb, c.bs, oh, ol, of, c.CIN, c.COUT, c.Kpad, NTt[ci], relu);
    };

    // 1) f1 = relu(conv(data 15->64))
    launch(0, dh, dl, 15, nullptr, nullptr, 0, nullptr, nullptr, f1h, f1l, nullptr, 1);
    // 2) feature = relu(conv(f1 64->128))
    launch(1, f1h, f1l, 64, nullptr, nullptr, 0, nullptr, nullptr, fth, ftl, nullptr, 1);
    // 3) offsets = conv(feature 128->81), fp32
    launch(2, fth, ftl, 128, nullptr, nullptr, 0, nullptr, nullptr, nullptr, nullptr, offs, 0);
    // 4) samples
    {
        long n = (long)Bn * Sn * HWn;
        trilerp_k<<<(unsigned)((n + 255) / 256), 256>>>(data, offs, samp, sph, spl);
    }
    // 5) h1 = relu(conv(concat(data15, feat128, samp81) 224->64))
    launch(3, dh, dl, 15, fth, ftl, 128, sph, spl, h1h, h1l, nullptr, 1);
    // 6) h2 = relu(conv(h1 64->64))
    launch(4, h1h, h1l, 64, nullptr, nullptr, 0, nullptr, nullptr, h2h, h2l, nullptr, 1);
    // 7) weights = conv(h2 64->27), fp32
    launch(5, h2h, h2l, 64, nullptr, nullptr, 0, nullptr, nullptr, nullptr, nullptr, wt, 0);
    // 8) combine
    {
        long n = (long)Bn * HWn;
        combine_k<<<(unsigned)((n + 255) / 256), 256>>>(samp, wt, res_i, outp);
    }
}

// round 8
// speedup vs baseline: 1.5649x; 1.2203x over previous
#include <cuda_runtime.h>
#include <cuda_fp16.h>

#define Hd 256
#define Wd 256
#define HWn 65536
#define Bn 4
#define Dn 5
#define Cn 3
#define Sn 27

#define RES_OFF  0L
#define OUT_OFF  (4L*3*3*HWn)
#define SAMP_OFF (OUT_OFF + 4L*3*HWn)

typedef unsigned short u16;
typedef unsigned int u32;

#define GUARD 16   // u16 guard elements before/after each plane region

// ---------------- fp16 hi/lo scratch planes (guarded, 16B aligned) --------
__device__ __align__(16) u16 g_data_h[4L*15*HWn + 2*GUARD],  g_data_l[4L*15*HWn + 2*GUARD];
__device__ __align__(16) u16 g_f1_h[4L*64*HWn + 2*GUARD],    g_f1_l[4L*64*HWn + 2*GUARD];
__device__ __align__(16) u16 g_feat_h[4L*128*HWn + 2*GUARD], g_feat_l[4L*128*HWn + 2*GUARD];
__device__ __align__(16) u16 g_samp_h[4L*81*HWn + 2*GUARD],  g_samp_l[4L*81*HWn + 2*GUARD];
__device__ __align__(16) u16 g_h1_h[4L*64*HWn + 2*GUARD],    g_h1_l[4L*64*HWn + 2*GUARD];
__device__ __align__(16) u16 g_h2_h[4L*64*HWn + 2*GUARD],    g_h2_l[4L*64*HWn + 2*GUARD];
__device__ float g_off[4L*81*HWn];
__device__ float g_wt[4L*27*HWn];
__device__ uint2 g_bfrag[6L*40960];   // fragment-ordered fp16 weights (hi only)

__device__ __forceinline__ u16 f16_hi(float v) {
    __half h = __float2half_rn(v);
    return *reinterpret_cast<u16*>(&h);
}
__device__ __forceinline__ float f16_f(u16 b) {
    __half h = *reinterpret_cast<__half*>(&b);
    return __half2float(h);
}
__device__ __forceinline__ u32 smem_u32(const void* p) {
    u32 a;
    asm("{ .reg .u64 t; cvta.to.shared.u64 t, %1; cvt.u32.u64 %0, t; }" : "=r"(a) : "l"(p));
    return a;
}
__device__ __forceinline__ void cp16(u32 dst, const void* src) {
    asm volatile("cp.async.cg.shared.global [%0], [%1], 16;" :: "r"(dst), "l"(src));
}
#define CP_COMMIT() asm volatile("cp.async.commit_group;")

// ---------------------------------------------------------------------------
__global__ void split_k(const float* __restrict__ src, u16* __restrict__ dh,
                        u16* __restrict__ dl, long n)
{
    long i = blockIdx.x * 256L + threadIdx.x;
    if (i >= n) return;
    float v = src[i];
    u16 h = f16_hi(v);
    dh[i] = h;
    dl[i] = f16_hi(v - f16_f(h));
}

// ---------------------------------------------------------------------------
// pack weights into mma B-fragment order (layout verified in rounds 6/7):
// element e = (q*NTt + ng)*32 + lane, q = 16-k step; lane g=lane>>2, t=lane&3;
// n = ng*8+g; kb = q*16+2t; uint2 = {b0,b1} with pairs (kb,kb+1),(kb+8,kb+9)
// ---------------------------------------------------------------------------
__global__ void packwf_k(const float* __restrict__ w, uint2* __restrict__ dst,
                         int COUT, int K, int Kpad, int NTt)
{
    long total = (long)(Kpad >> 4) * NTt * 32;
    long e = blockIdx.x * 256L + threadIdx.x;
    if (e >= total) return;
    int lane = (int)(e & 31);
    long r = e >> 5;
    int ng = (int)(r % NTt);
    int q  = (int)(r / NTt);
    int g = lane >> 2, t = lane & 3;
    int n = ng * 8 + g;
    int kb = q * 16 + 2 * t;

    float v[4];
    int kk[4] = {kb, kb + 1, kb + 8, kb + 9};
#pragma unroll
    for (int i = 0; i < 4; i++)
        v[i] = (n < COUT && kk[i] < K) ? w[(long)n * K + kk[i]] : 0.f;

    u16 h[4];
#pragma unroll
    for (int i = 0; i < 4; i++) h[i] = f16_hi(v[i]);
    uint2 o;
    o.x = (u32)h[0] | ((u32)h[1] << 16);
    o.y = (u32)h[2] | ((u32)h[3] << 16);
    dst[e] = o;
}

// ---------------------------------------------------------------------------
__device__ __forceinline__ void mma16816(float d[4], const u32 a[4], u32 b0, u32 b1)
{
    asm volatile(
        "mma.sync.aligned.m16n8k16.row.col.f32.f16.f16.f32 "
        "{%0,%1,%2,%3}, {%4,%5,%6,%7}, {%8,%9}, {%0,%1,%2,%3};"
        : "+f"(d[0]), "+f"(d[1]), "+f"(d[2]), "+f"(d[3])
        : "r"(a[0]), "r"(a[1]), "r"(a[2]), "r"(a[3]), "r"(b0), "r"(b1));
}

// ---------------------------------------------------------------------------
// Implicit-GEMM 3x3 conv, M=256 (one full image row), N=64 slice per block.
// A: raw input rows (cin,kh) with +-8 halo in SMEM (fp16 hi + lo planes);
// shift applied at fragment load: At[k][m] = Raw[tt(k)][m + kw(k) + 7].
// B: fragment-ordered uint2 (fp16 hi) staged in SMEM. cp.async double-buffered.
// 2-term emulation: D = Ah*Bh + Al*Bh.
// ---------------------------------------------------------------------------
#define A_ROWS  22
#define A_PITCH 272                         // u16 per raw row
#define A_PLANE (A_ROWS*A_PITCH)            // u16 per plane
#define A_BUFB  (2*A_PLANE*2)               // bytes per A buffer (hi+lo)

template<int NT>
__global__ void __launch_bounds__(256)
convM_k(const u16* __restrict__ s0h, const u16* __restrict__ s0l, int c0,
        const u16* __restrict__ s1h, const u16* __restrict__ s1l, int c1,
        const u16* __restrict__ s2h, const u16* __restrict__ s2l,
        const uint2* __restrict__ bfrag,
        const float* __restrict__ bias,
        u16* __restrict__ dsth, u16* __restrict__ dstl, float* __restrict__ dstf,
        int CIN, int COUT, int Kpad, int NTt, int relu)
{
    extern __shared__ char sm[];
    const u32 smbase = smem_u32(sm);
    const int BSZB = 128 * NT * 8;           // bytes per B buffer (uint2 frags)

    const int tid = threadIdx.x;
    const int wid = tid >> 5;
    const int lane = tid & 31;
    const int g = lane >> 2;
    const int t = lane & 3;
    const int b = blockIdx.x >> 8;
    const int h = blockIdx.x & 255;
    const int slice = blockIdx.y;
    const int mb = wid * 16;

    const int c01 = c0 + c1;
    const int c2 = CIN - c01;
    const int nchunk = Kpad >> 6;

    float acc[2][NT][4];
#pragma unroll
    for (int mt = 0; mt < 2; mt++)
#pragma unroll
        for (int i = 0; i < NT; i++)
#pragma unroll
            for (int j = 0; j < 4; j++) acc[mt][i][j] = 0.f;

    // ---- fill one chunk's A raw rows + B fragments into buffer `buf` ----
    auto fill = [&](int kc, int buf) {
        const int K0 = kc * 64;
        const int T0 = (K0 * 21846) >> 16;
        const u32 abase = smbase + buf * A_BUFB;
        // A: 22 rows x 34 16B-chunks x 2 planes
        for (int e = tid; e < A_ROWS * 34 * 2; e += 256) {
            int tt = e / 68;
            int r = e - tt * 68;
            int pl = r >= 34;
            int j = r - pl * 34;
            int T = T0 + tt;
            int cin = T / 3;
            int kh = T - cin * 3;
            int hh = h + kh - 1;
            u32 dst = abase + (u32)(pl * A_PLANE + tt * A_PITCH + j * 8) * 2;
            if (cin < CIN && (unsigned)hh < 256u) {
                const u16* sp;
                if (cin < c0)       sp = (pl ? s0l : s0h) + ((long)b * c0 + cin) * HWn;
                else if (cin < c01) sp = (pl ? s1l : s1h) + ((long)b * c1 + (cin - c0)) * HWn;
                else                sp = (pl ? s2l : s2h) + ((long)b * c2 + (cin - c01)) * HWn;
                cp16(dst, sp + (long)hh * 256 + j * 8 - 8);
            } else {
                asm volatile("st.shared.v4.b32 [%0], {%1,%1,%1,%1};" :: "r"(dst), "r"(0u));
            }
        }
        // B: 128*NT uint2 in fragment order; 16B = 2 consecutive lane-frags.
        const u32 bbase = smbase + 2 * A_BUFB + buf * BSZB;
        const int q0 = kc * 4;
        for (int e = tid; e < 64 * NT; e += 256) {
            int ks = e / (NT * 16);
            int r = e - ks * (NT * 16);     // 16B unit within this ks
            const uint2* src = bfrag + ((long)(q0 + ks) * NTt + slice * 8) * 32 + r * 2;
            cp16(bbase + (u32)e * 16, src);
        }
    };

    fill(0, 0);
    CP_COMMIT();

    for (int kc = 0; kc < nchunk; ++kc) {
        const int buf = kc & 1;
        if (kc + 1 < nchunk) {
            fill(kc + 1, buf ^ 1);
            CP_COMMIT();
            asm volatile("cp.async.wait_group 1;");
        } else {
            asm volatile("cp.async.wait_group 0;");
        }
        __syncthreads();

        // edge fixups: zero halo cells ww=-1 (idx 7) and ww=256 (idx 264)
        u16* Rh = (u16*)(sm + buf * A_BUFB);
        u16* Rl = Rh + A_PLANE;
        if (tid < A_ROWS) {
            Rh[tid * A_PITCH + 7] = 0;   Rh[tid * A_PITCH + 264] = 0;
            Rl[tid * A_PITCH + 7] = 0;   Rl[tid * A_PITCH + 264] = 0;
        }
        __syncthreads();

        const uint2* Bsm = (const uint2*)(sm + 2 * A_BUFB + buf * BSZB);
        const int K0 = kc * 64;
        const int T0 = (K0 * 21846) >> 16;

#pragma unroll
        for (int ks = 0; ks < 4; ks++) {
            int kg = K0 + ks * 16 + 2 * t;
            int Ta = (kg * 21846) >> 16;        int kwa = kg - Ta * 3;
            int Tb = ((kg + 1) * 21846) >> 16;  int kwb = kg + 1 - Tb * 3;
            int Tc = ((kg + 8) * 21846) >> 16;  int kwc = kg + 8 - Tc * 3;
            int Td = ((kg + 9) * 21846) >> 16;  int kwd = kg + 9 - Td * 3;
            int ra = (Ta - T0) * A_PITCH + kwa + 7;
            int rb = (Tb - T0) * A_PITCH + kwb + 7;
            int rc = (Tc - T0) * A_PITCH + kwc + 7;
            int rd = (Td - T0) * A_PITCH + kwd + 7;

            u32 ah[2][4], al[2][4];
#pragma unroll
            for (int mt = 0; mt < 2; mt++) {
                int m = mb + mt * 128 + g;
                ah[mt][0] = (u32)Rh[ra + m]     | ((u32)Rh[rb + m]     << 16);
                ah[mt][1] = (u32)Rh[ra + m + 8] | ((u32)Rh[rb + m + 8] << 16);
                ah[mt][2] = (u32)Rh[rc + m]     | ((u32)Rh[rd + m]     << 16);
                ah[mt][3] = (u32)Rh[rc + m + 8] | ((u32)Rh[rd + m + 8] << 16);
                al[mt][0] = (u32)Rl[ra + m]     | ((u32)Rl[rb + m]     << 16);
                al[mt][1] = (u32)Rl[ra + m + 8] | ((u32)Rl[rb + m + 8] << 16);
                al[mt][2] = (u32)Rl[rc + m]     | ((u32)Rl[rd + m]     << 16);
                al[mt][3] = (u32)Rl[rc + m + 8] | ((u32)Rl[rd + m + 8] << 16);
            }
            const uint2* Bp = Bsm + ks * NT * 32 + lane;
#pragma unroll
            for (int nt = 0; nt < NT; nt++) {
                uint2 bv = Bp[nt * 32];
                mma16816(acc[0][nt], ah[0], bv.x, bv.y);
                mma16816(acc[0][nt], al[0], bv.x, bv.y);
                mma16816(acc[1][nt], ah[1], bv.x, bv.y);
                mma16816(acc[1][nt], al[1], bv.x, bv.y);
            }
        }
        __syncthreads();   // protect buf from next prefetch overwrite
    }

    // ---- epilogue ----
#pragma unroll
    for (int mt = 0; mt < 2; mt++)
#pragma unroll
        for (int nt = 0; nt < NT; nt++) {
            int n0 = slice * 64 + nt * 8 + t * 2;
#pragma unroll
            for (int i = 0; i < 4; i++) {
                int n = n0 + (i & 1);
                if (n >= COUT) continue;
                int m = mb + mt * 128 + g + ((i & 2) ? 8 : 0);
                float v = acc[mt][nt][i] + bias[n];
                if (relu) v = fmaxf(v, 0.f);
                long o = ((long)b * COUT + n) * HWn + (long)h * 256 + m;
                if (dsth) {
                    u16 hv = f16_hi(v);
                    dsth[o] = hv;
                    dstl[o] = f16_hi(v - f16_f(hv));
                }
                if (dstf) dstf[o] = v;
            }
        }
}

// ---------------------------------------------------------------------------
__global__ void trilerp_k(const float* __restrict__ data,
                          const float* __restrict__ off,
                          float* __restrict__ samp,
                          u16* __restrict__ sh, u16* __restrict__ sl)
{
    long idx = blockIdx.x * 256L + threadIdx.x;
    if (idx >= (long)Bn * Sn * HWn) return;
    int hw = (int)(idx % HWn);
    int s  = (int)((idx / HWn) % Sn);
    int b  = (int)(idx / ((long)Sn * HWn));
    int h = hw >> 8, w = hw & 255;

    int kd = s / 9 - 1, kh = (s / 3) % 3 - 1, kw = s % 3 - 1;

    const float* ob = off + ((long)b * (Sn * 3) + s * 3) * HWn + hw;
    float pd = 2.0f + (float)kd + ob[0];
    float ph = (float)h + (float)kh + ob[HWn];
    float pw = (float)w + (float)kw + ob[2L * HWn];
    pd = fminf(fmaxf(pd, 0.f), (float)(Dn - 1));
    ph = fminf(fmaxf(ph, 0.f), (float)(Hd - 1));
    pw = fminf(fmaxf(pw, 0.f), (float)(Wd - 1));

    float d0f = floorf(pd), h0f = floorf(ph), w0f = floorf(pw);
    float fd = pd - d0f, fh = ph - h0f, fw = pw - w0f;
    int d0 = (int)d0f, h0 = (int)h0f, w0 = (int)w0f;
    int d1 = min(d0 + 1, Dn - 1), h1 = min(h0 + 1, Hd - 1), w1 = min(w0 + 1, Wd - 1);

    float gd0 = 1.f - fd, gh0 = 1.f - fh, gw0 = 1.f - fw;
    float w000 = gd0*gh0*gw0, w001 = gd0*gh0*fw, w010 = gd0*fh*gw0, w011 = gd0*fh*fw;
    float w100 = fd*gh0*gw0,  w101 = fd*gh0*fw,  w110 = fd*fh*gw0,  w111 = fd*fh*fw;

    long i00 = (long)h0 * Wd + w0, i01 = (long)h0 * Wd + w1;
    long i10 = (long)h1 * Wd + w0, i11 = (long)h1 * Wd + w1;

#pragma unroll
    for (int c = 0; c < Cn; c++) {
        const float* p0 = data + (((long)b * Dn + d0) * Cn + c) * HWn;
        const float* p1 = data + (((long)b * Dn + d1) * Cn + c) * HWn;
        float v = w000*p0[i00] + w001*p0[i01] + w010*p0[i10] + w011*p0[i11]
                + w100*p1[i00] + w101*p1[i01] + w110*p1[i10] + w111*p1[i11];
        long o = (((long)b * Sn + s) * Cn + c) * HWn + hw;
        samp[o] = v;
        u16 hv = f16_hi(v);
        sh[o] = hv;
        sl[o] = f16_hi(v - f16_f(hv));
    }
}

// ---------------------------------------------------------------------------
__global__ void combine_k(const float* __restrict__ samp,
                          const float* __restrict__ wts,
                          float* __restrict__ res_i, float* __restrict__ outp)
{
    long idx = blockIdx.x * 256L + threadIdx.x;
    if (idx >= (long)Bn * HWn) return;
    int hw = (int)(idx % HWn);
    int b  = (int)(idx / HWn);

    float wv[Sn];
#pragma unroll
    for (int s = 0; s < Sn; s++) wv[s] = wts[((long)b * Sn + s) * HWn + hw];

    float o[3] = {0.f, 0.f, 0.f};
#pragma unroll
    for (int g = 0; g < 3; g++) {
#pragma unroll
        for (int c = 0; c < 3; c++) {
            float r = 0.f;
#pragma unroll
            for (int k = 0; k < 9; k++) {
                int s = g * 9 + k;
                r += samp[(((long)b * Sn + s) * Cn + c) * HWn + hw] * wv[s];
            }
            r *= 3.0f;
            res_i[(((long)b * 3 + g) * 3 + c) * HWn + hw] = r;
            o[c] += r;
        }
    }
#pragma unroll
    for (int c = 0; c < 3; c++)
        outp[((long)b * 3 + c) * HWn + hw] = o[c] * (1.0f / 3.0f);
}

// ---------------------------------------------------------------------------
extern "C" void kernel_launch(void* const* d_in, const int* in_sizes, int n_in,
                              void* d_out, int out_size)
{
    const float* data   = (const float*)d_in[0];
    const float* enc_w1 = (const float*)d_in[1];
    const float* enc_b1 = (const float*)d_in[2];
    const float* enc_w2 = (const float*)d_in[3];
    const float* enc_b2 = (const float*)d_in[4];
    const float* off_w  = (const float*)d_in[5];
    const float* off_b  = (const float*)d_in[6];
    const float* wc_w1  = (const float*)d_in[7];
    const float* wc_b1  = (const float*)d_in[8];
    const float* wc_w2  = (const float*)d_in[9];
    const float* wc_b2  = (const float*)d_in[10];
    const float* wc_w3  = (const float*)d_in[11];
    const float* wc_b3  = (const float*)d_in[12];
    float* out = (float*)d_out;

    u16 *dh, *dl, *f1h, *f1l, *fth, *ftl, *sph, *spl, *h1h, *h1l, *h2h, *h2l;
    float *offs, *wt;
    uint2* bf;
    cudaGetSymbolAddress((void**)&dh,  g_data_h);  cudaGetSymbolAddress((void**)&dl,  g_data_l);
    cudaGetSymbolAddress((void**)&f1h, g_f1_h);    cudaGetSymbolAddress((void**)&f1l, g_f1_l);
    cudaGetSymbolAddress((void**)&fth, g_feat_h);  cudaGetSymbolAddress((void**)&ftl, g_feat_l);
    cudaGetSymbolAddress((void**)&sph, g_samp_h);  cudaGetSymbolAddress((void**)&spl, g_samp_l);
    cudaGetSymbolAddress((void**)&h1h, g_h1_h);    cudaGetSymbolAddress((void**)&h1l, g_h1_l);
    cudaGetSymbolAddress((void**)&h2h, g_h2_h);    cudaGetSymbolAddress((void**)&h2l, g_h2_l);
    cudaGetSymbolAddress((void**)&offs, g_off);    cudaGetSymbolAddress((void**)&wt,  g_wt);
    cudaGetSymbolAddress((void**)&bf,  g_bfrag);
    // guarded bases
    dh += GUARD; dl += GUARD; f1h += GUARD; f1l += GUARD; fth += GUARD; ftl += GUARD;
    sph += GUARD; spl += GUARD; h1h += GUARD; h1l += GUARD; h2h += GUARD; h2l += GUARD;

    float* res_i = out + RES_OFF;
    float* outp  = out + OUT_OFF;
    float* samp  = out + SAMP_OFF;

    // conv table: {w, b, CIN, COUT, Kpad, slices}
    struct CV { const float* w; const float* bs; int CIN, COUT, Kpad, slices; };
    CV cv[6] = {
        {enc_w1, enc_b1,  15,  64,  192, 1},
        {enc_w2, enc_b2,  64, 128,  576, 2},
        {off_w,  off_b,  128,  81, 1152, 2},
        {wc_w1,  wc_b1,  224,  64, 2048, 1},
        {wc_w2,  wc_b2,   64,  64,  576, 1},
        {wc_w3,  wc_b3,   64,  27,  576, 1},
    };
    int NTt[6] = {8, 16, 16, 8, 8, 4};

    // 0) split input to fp16 hi/lo
    {
        long n = 4L * 15 * HWn;
        split_k<<<(unsigned)((n + 255) / 256), 256>>>(data, dh, dl, n);
    }
    // pack weights into fragment order
    for (int i = 0; i < 6; i++) {
        long n = (long)(cv[i].Kpad >> 4) * NTt[i] * 32;
        packwf_k<<<(unsigned)((n + 255) / 256), 256>>>(cv[i].w, bf + i * 40960L,
                                                       cv[i].COUT, cv[i].CIN * 9,
                                                       cv[i].Kpad, NTt[i]);
    }

    const int DSM8 = 2 * A_BUFB + 2 * 128 * 8 * 8;   // 47872 + 16384 = 64256
    const int DSM4 = 2 * A_BUFB + 2 * 128 * 4 * 8;   // 47872 +  8192 = 56064
    cudaFuncSetAttribute(convM_k<8>, cudaFuncAttributeMaxDynamicSharedMemorySize, DSM8);
    cudaFuncSetAttribute(convM_k<4>, cudaFuncAttributeMaxDynamicSharedMemorySize, DSM4);

    auto launch = [&](int ci, const u16* a0h, const u16* a0l, int c0,
                      const u16* a1h, const u16* a1l, int c1,
                      const u16* a2h, const u16* a2l,
                      u16* oh, u16* ol, float* of, int relu) {
        const CV& c = cv[ci];
        const uint2* wb = bf + ci * 40960L;
        dim3 grid(1024, c.slices);
        if (NTt[ci] == 4)
            convM_k<4><<<grid, 256, DSM4>>>(a0h, a0l, c0, a1h, a1l, c1, a2h, a2l,
                wb, c.bs, oh, ol, of, c.CIN, c.COUT, c.Kpad, NTt[ci], relu);
        else
            convM_k<8><<<grid, 256, DSM8>>>(a0h, a0l, c0, a1h, a1l, c1, a2h, a2l,
                wb, c.bs, oh, ol, of, c.CIN, c.COUT, c.Kpad, NTt[ci], relu);
    };

    // 1) f1 = relu(conv(data 15->64))
    launch(0, dh, dl, 15, nullptr, nullptr, 0, nullptr, nullptr, f1h, f1l, nullptr, 1);
    // 2) feature = relu(conv(f1 64->128))
    launch(1, f1h, f1l, 64, nullptr, nullptr, 0, nullptr, nullptr, fth, ftl, nullptr, 1);
    // 3) offsets = conv(feature 128->81), fp32
    launch(2, fth, ftl, 128, nullptr, nullptr, 0, nullptr, nullptr, nullptr, nullptr, offs, 0);
    // 4) samples
    {
        long n = (long)Bn * Sn * HWn;
        trilerp_k<<<(unsigned)((n + 255) / 256), 256>>>(data, offs, samp, sph, spl);
    }
    // 5) h1 = relu(conv(concat(data15, feat128, samp81) 224->64))
    launch(3, dh, dl, 15, fth, ftl, 128, sph, spl, h1h, h1l, nullptr, 1);
    // 6) h2 = relu(conv(h1 64->64))
    launch(4, h1h, h1l, 64, nullptr, nullptr, 0, nullptr, nullptr, h2h, h2l, nullptr, 1);
    // 7) weights = conv(h2 64->27), fp32
    launch(5, h2h, h2l, 64, nullptr, nullptr, 0, nullptr, nullptr, nullptr, nullptr, wt, 0);
    // 8) combine
    {
        long n = (long)Bn * HWn;
        combine_k<<<(unsigned)((n + 255) / 256), 256>>>(samp, wt, res_i, outp);
    }
}

// round 10
// speedup vs baseline: 1.7887x; 1.1430x over previous
#include <cuda_runtime.h>
#include <cuda_fp16.h>

#define Hd 256
#define Wd 256
#define HWn 65536
#define Bn 4
#define Dn 5
#define Cn 3
#define Sn 27

#define RES_OFF  0L
#define OUT_OFF  (4L*3*3*HWn)
#define SAMP_OFF (OUT_OFF + 4L*3*HWn)

typedef unsigned short u16;
typedef unsigned int u32;

#define GUARD 16   // u32 guard elements before/after each plane region

// ---------------- interleaved fp16 hi|lo planes (u32/elem, guarded) -------
__device__ __align__(16) u32 g_data_w[4L*15*HWn + 2*GUARD];
__device__ __align__(16) u32 g_f1_w[4L*64*HWn + 2*GUARD];
__device__ __align__(16) u32 g_feat_w[4L*128*HWn + 2*GUARD];
__device__ __align__(16) u32 g_samp_w[4L*81*HWn + 2*GUARD];
__device__ __align__(16) u32 g_h1_w[4L*64*HWn + 2*GUARD];
__device__ __align__(16) u32 g_h2_w[4L*64*HWn + 2*GUARD];
__device__ float g_off[4L*81*HWn];
__device__ float g_wt[4L*27*HWn];
__device__ uint2 g_bfh[6L*40960];   // fragment-ordered fp16 weights, hi
__device__ uint2 g_bfl[6L*40960];   // fragment-ordered fp16 weights, lo

__device__ __forceinline__ u16 f16_hi(float v) {
    __half h = __float2half_rn(v);
    return *reinterpret_cast<u16*>(&h);
}
__device__ __forceinline__ float f16_f(u16 b) {
    __half h = *reinterpret_cast<__half*>(&b);
    return __half2float(h);
}
__device__ __forceinline__ u32 pack_hilo(float v) {
    u16 hv = f16_hi(v);
    u16 lv = f16_hi(v - f16_f(hv));
    return (u32)hv | ((u32)lv << 16);
}
__device__ __forceinline__ u32 smem_u32(const void* p) {
    u32 a;
    asm("{ .reg .u64 t; cvta.to.shared.u64 t, %1; cvt.u32.u64 %0, t; }" : "=r"(a) : "l"(p));
    return a;
}
__device__ __forceinline__ void cp16(u32 dst, const void* src) {
    asm volatile("cp.async.cg.shared.global [%0], [%1], 16;" :: "r"(dst), "l"(src));
}
#define CP_COMMIT() asm volatile("cp.async.commit_group;")

// ---------------------------------------------------------------------------
__global__ void split_k(const float* __restrict__ src, u32* __restrict__ dw, long n)
{
    long i = blockIdx.x * 256L + threadIdx.x;
    if (i >= n) return;
    dw[i] = pack_hilo(src[i]);
}

// ---------------------------------------------------------------------------
// pack ALL conv weights into mma B-fragment order (hi + lo arrays).
// Fragment layout (verified R6-R8): element le = (q*NTt + ng)*32 + lane,
// g=lane>>2, t=lane&3; n = ng*8+g; kb = q*16+2t;
// uint2 = {b0,b1}, pairs (kb,kb+1),(kb+8,kb+9).
// ---------------------------------------------------------------------------
__global__ void packall_k(const float* w0, const float* w1, const float* w2,
                          const float* w3, const float* w4, const float* w5,
                          uint2* __restrict__ bh, uint2* __restrict__ bl)
{
    long e = blockIdx.x * 256L + threadIdx.x;
    if (e >= 95744) return;
    int ci; long base;
    if      (e < 3072)  { ci = 0; base = 0; }
    else if (e < 21504) { ci = 1; base = 3072; }
    else if (e < 49152) { ci = 2; base = 21504; }
    else if (e < 81920) { ci = 3; base = 49152; }
    else if (e < 91136) { ci = 4; base = 81920; }
    else                { ci = 5; base = 91136; }
    const float* wp = ci == 0 ? w0 : ci == 1 ? w1 : ci == 2 ? w2
                    : ci == 3 ? w3 : ci == 4 ? w4 : w5;
    const int COUTs[6] = {64, 128, 81, 64, 64, 27};
    const int Ks[6]    = {135, 576, 1152, 2016, 576, 576};
    const int NTts[6]  = {8, 16, 12, 8, 8, 4};
    int COUT = COUTs[ci], K = Ks[ci], NTt = NTts[ci];

    long le = e - base;
    int lane = (int)(le & 31);
    long r = le >> 5;
    int ng = (int)(r % NTt);
    int q  = (int)(r / NTt);
    int g = lane >> 2, t = lane & 3;
    int n = ng * 8 + g;
    int kb = q * 16 + 2 * t;

    float v[4];
    int kk[4] = {kb, kb + 1, kb + 8, kb + 9};
#pragma unroll
    for (int i = 0; i < 4; i++)
        v[i] = (n < COUT && kk[i] < K) ? wp[(long)n * K + kk[i]] : 0.f;

    u16 h[4], l[4];
#pragma unroll
    for (int i = 0; i < 4; i++) {
        h[i] = f16_hi(v[i]);
        l[i] = f16_hi(v[i] - f16_f(h[i]));
    }
    long di = (long)ci * 40960 + le;
    bh[di] = make_uint2((u32)h[0] | ((u32)h[1] << 16), (u32)h[2] | ((u32)h[3] << 16));
    bl[di] = make_uint2((u32)l[0] | ((u32)l[1] << 16), (u32)l[2] | ((u32)l[3] << 16));
}

// ---------------------------------------------------------------------------
__device__ __forceinline__ void mma16816(float d[4], const u32 a[4], u32 b0, u32 b1)
{
    asm volatile(
        "mma.sync.aligned.m16n8k16.row.col.f32.f16.f16.f32 "
        "{%0,%1,%2,%3}, {%4,%5,%6,%7}, {%8,%9}, {%0,%1,%2,%3};"
        : "+f"(d[0]), "+f"(d[1]), "+f"(d[2]), "+f"(d[3])
        : "r"(a[0]), "r"(a[1]), "r"(a[2]), "r"(a[3]), "r"(b0), "r"(b1));
}

// ---------------------------------------------------------------------------
// Implicit-GEMM 3x3 conv, M=256 (full image row), N = NT*8 at slice*64 offset.
// A: raw input rows (cin,kh) with 4-u32 halo each side, interleaved {hi,lo};
//    SMEM u32 index i corresponds to global ww = i - 4, so fragment offset
//    for kernel column kw (0..2, meaning ww shift kw-1) is kw + 3.
// B: fragment-ordered uint2 (hi; + lo when TERMS==3). cp.async double-buffered.
// TERMS==2: D = Ah*Bh + Al*Bh.  TERMS==3: + Ah*Bl.
// ---------------------------------------------------------------------------
#define A_ROWS   22
#define A_PITCHW 272                         // u32 per raw row
#define A_BUFB   (A_ROWS*A_PITCHW*4)         // 23936 bytes per A buffer

template<int NT, int TERMS>
__global__ void __launch_bounds__(256)
convM_k(const u32* __restrict__ s0, int c0,
        const u32* __restrict__ s1, int c1,
        const u32* __restrict__ s2,
        const uint2* __restrict__ bfh, const uint2* __restrict__ bfl,
        const float* __restrict__ bias,
        u32* __restrict__ dstw, float* __restrict__ dstf,
        int CIN, int COUT, int Kpad, int NTt, int slice, int relu)
{
    extern __shared__ char sm[];
    const u32 smbase = smem_u32(sm);
    const int BSZB = 128 * NT * 8;           // bytes per B buffer (hi or lo)

    const int tid = threadIdx.x;
    const int wid = tid >> 5;
    const int lane = tid & 31;
    const int g = lane >> 2;
    const int t = lane & 3;
    const int b = blockIdx.x >> 8;
    const int h = blockIdx.x & 255;
    const int mb = wid * 16;

    const int c01 = c0 + c1;
    const int c2 = CIN - c01;
    const int nchunk = Kpad >> 6;

    float acc[2][NT][4];
#pragma unroll
    for (int mt = 0; mt < 2; mt++)
#pragma unroll
        for (int i = 0; i < NT; i++)
#pragma unroll
            for (int j = 0; j < 4; j++) acc[mt][i][j] = 0.f;

    // ---- fill one chunk's A raw rows + B fragments into buffer `buf` ----
    auto fill = [&](int kc, int buf) {
        const int K0 = kc * 64;
        const int T0 = (int)(((unsigned)K0 * 21846u) >> 16);
        const u32 abase = smbase + buf * A_BUFB;
        // A: 22 rows x 68 16B-chunks (u32 interleaved plane)
        for (int e = tid; e < A_ROWS * 68; e += 256) {
            int tt = e / 68;
            int j = e - tt * 68;
            int T = T0 + tt;
            int cin = (int)(((unsigned)T * 21846u) >> 16);
            int kh = T - cin * 3;
            int hh = h + kh - 1;
            u32 dst = abase + (u32)(tt * 1088 + j * 16);
            if (cin < CIN && (unsigned)hh < 256u) {
                const u32* sp;
                if (cin < c0)       sp = s0 + ((long)b * c0 + cin) * HWn;
                else if (cin < c01) sp = s1 + ((long)b * c1 + (cin - c0)) * HWn;
                else                sp = s2 + ((long)b * c2 + (cin - c01)) * HWn;
                cp16(dst, sp + (long)hh * 256 + j * 4 - 4);
            } else {
                asm volatile("st.shared.v4.b32 [%0], {%1,%1,%1,%1};" :: "r"(dst), "r"(0u));
            }
        }
        // B fragments (hi, + lo when 3-term)
        const u32 bhb = smbase + 2 * A_BUFB + buf * BSZB;
        const int q0 = kc * 4;
        for (int e = tid; e < 64 * NT; e += 256) {
            int ks = e / (NT * 16);
            int r = e - ks * (NT * 16);
            long fo = ((long)(q0 + ks) * NTt + slice * 8) * 32 + r * 2;
            cp16(bhb + (u32)e * 16, bfh + fo);
            if (TERMS == 3)
                cp16(bhb + 2 * BSZB + (u32)e * 16, bfl + fo);
        }
    };

    fill(0, 0);
    CP_COMMIT();

    for (int kc = 0; kc < nchunk; ++kc) {
        const int buf = kc & 1;
        if (kc + 1 < nchunk) {
            fill(kc + 1, buf ^ 1);
            CP_COMMIT();
            asm volatile("cp.async.wait_group 1;");
        } else {
            asm volatile("cp.async.wait_group 0;");
        }
        __syncthreads();

        // edge fixups: zero halo cells ww=-1 (index 3) and ww=256 (index 260)
        u32* Aw = (u32*)(sm + buf * A_BUFB);
        if (tid < A_ROWS) {
            Aw[tid * A_PITCHW + 3] = 0;
            Aw[tid * A_PITCHW + 260] = 0;
        }
        __syncthreads();

        const uint2* Bh = (const uint2*)(sm + 2 * A_BUFB + buf * BSZB);
        const uint2* Bl = (const uint2*)(sm + 2 * A_BUFB + 2 * BSZB + buf * BSZB);
        const int K0 = kc * 64;
        const int T0 = (int)(((unsigned)K0 * 21846u) >> 16);

#pragma unroll
        for (int ks = 0; ks < 4; ks++) {
            int kg = K0 + ks * 16 + 2 * t;
            int Ta = (int)(((unsigned)kg * 21846u) >> 16);        int kwa = kg - Ta * 3;
            int Tb = (int)(((unsigned)(kg + 1) * 21846u) >> 16);  int kwb = kg + 1 - Tb * 3;
            int Tc = (int)(((unsigned)(kg + 8) * 21846u) >> 16);  int kwc = kg + 8 - Tc * 3;
            int Td = (int)(((unsigned)(kg + 9) * 21846u) >> 16);  int kwd = kg + 9 - Td * 3;
            int ra = (Ta - T0) * A_PITCHW + kwa + 3;
            int rb = (Tb - T0) * A_PITCHW + kwb + 3;
            int rc = (Tc - T0) * A_PITCHW + kwc + 3;
            int rd = (Td - T0) * A_PITCHW + kwd + 3;

            u32 ah[2][4], al[2][4];
#pragma unroll
            for (int mt = 0; mt < 2; mt++) {
                int m = mb + mt * 128 + g;
                u32 x0 = Aw[ra + m],     y0 = Aw[rb + m];
                u32 x1 = Aw[ra + m + 8], y1 = Aw[rb + m + 8];
                u32 x2 = Aw[rc + m],     y2 = Aw[rd + m];
                u32 x3 = Aw[rc + m + 8], y3 = Aw[rd + m + 8];
                ah[mt][0] = __byte_perm(x0, y0, 0x5410); al[mt][0] = __byte_perm(x0, y0, 0x7632);
                ah[mt][1] = __byte_perm(x1, y1, 0x5410); al[mt][1] = __byte_perm(x1, y1, 0x7632);
                ah[mt][2] = __byte_perm(x2, y2, 0x5410); al[mt][2] = __byte_perm(x2, y2, 0x7632);
                ah[mt][3] = __byte_perm(x3, y3, 0x5410); al[mt][3] = __byte_perm(x3, y3, 0x7632);
            }
            const uint2* Bph = Bh + ks * NT * 32 + lane;
            const uint2* Bpl = Bl + ks * NT * 32 + lane;
#pragma unroll
            for (int nt = 0; nt < NT; nt++) {
                uint2 bvh = Bph[nt * 32];
                mma16816(acc[0][nt], ah[0], bvh.x, bvh.y);
                mma16816(acc[0][nt], al[0], bvh.x, bvh.y);
                mma16816(acc[1][nt], ah[1], bvh.x, bvh.y);
                mma16816(acc[1][nt], al[1], bvh.x, bvh.y);
                if (TERMS == 3) {
                    uint2 bvl = Bpl[nt * 32];
                    mma16816(acc[0][nt], ah[0], bvl.x, bvl.y);
                    mma16816(acc[1][nt], ah[1], bvl.x, bvl.y);
                }
            }
        }
        __syncthreads();   // protect buf from next prefetch overwrite
    }

    // ---- epilogue ----
#pragma unroll
    for (int mt = 0; mt < 2; mt++)
#pragma unroll
        for (int nt = 0; nt < NT; nt++) {
            int n0 = slice * 64 + nt * 8 + t * 2;
#pragma unroll
            for (int i = 0; i < 4; i++) {
                int n = n0 + (i & 1);
                if (n >= COUT) continue;
                int m = mb + mt * 128 + g + ((i & 2) ? 8 : 0);
                float v = acc[mt][nt][i] + bias[n];
                if (relu) v = fmaxf(v, 0.f);
                long o = ((long)b * COUT + n) * HWn + (long)h * 256 + m;
                if (dstw) dstw[o] = pack_hilo(v);
                if (dstf) dstf[o] = v;
            }
        }
}

// ---------------------------------------------------------------------------
__global__ void trilerp_k(const float* __restrict__ data,
                          const float* __restrict__ off,
                          float* __restrict__ samp, u32* __restrict__ sw)
{
    long idx = blockIdx.x * 256L + threadIdx.x;
    if (idx >= (long)Bn * Sn * HWn) return;
    int hw = (int)(idx % HWn);
    int s  = (int)((idx / HWn) % Sn);
    int b  = (int)(idx / ((long)Sn * HWn));
    int h = hw >> 8, w = hw & 255;

    int kd = s / 9 - 1, kh = (s / 3) % 3 - 1, kw = s % 3 - 1;

    const float* ob = off + ((long)b * (Sn * 3) + s * 3) * HWn + hw;
    float pd = 2.0f + (float)kd + ob[0];
    float ph = (float)h + (float)kh + ob[HWn];
    float pw = (float)w + (float)kw + ob[2L * HWn];
    pd = fminf(fmaxf(pd, 0.f), (float)(Dn - 1));
    ph = fminf(fmaxf(ph, 0.f), (float)(Hd - 1));
    pw = fminf(fmaxf(pw, 0.f), (float)(Wd - 1));

    float d0f = floorf(pd), h0f = floorf(ph), w0f = floorf(pw);
    float fd = pd - d0f, fh = ph - h0f, fw = pw - w0f;
    int d0 = (int)d0f, h0 = (int)h0f, w0 = (int)w0f;
    int d1 = min(d0 + 1, Dn - 1), h1 = min(h0 + 1, Hd - 1), w1 = min(w0 + 1, Wd - 1);

    float gd0 = 1.f - fd, gh0 = 1.f - fh, gw0 = 1.f - fw;
    float w000 = gd0*gh0*gw0, w001 = gd0*gh0*fw, w010 = gd0*fh*gw0, w011 = gd0*fh*fw;
    float w100 = fd*gh0*gw0,  w101 = fd*gh0*fw,  w110 = fd*fh*gw0,  w111 = fd*fh*fw;

    long i00 = (long)h0 * Wd + w0, i01 = (long)h0 * Wd + w1;
    long i10 = (long)h1 * Wd + w0, i11 = (long)h1 * Wd + w1;

#pragma unroll
    for (int c = 0; c < Cn; c++) {
        const float* p0 = data + (((long)b * Dn + d0) * Cn + c) * HWn;
        const float* p1 = data + (((long)b * Dn + d1) * Cn + c) * HWn;
        float v = w000*p0[i00] + w001*p0[i01] + w010*p0[i10] + w011*p0[i11]
                + w100*p1[i00] + w101*p1[i01] + w110*p1[i10] + w111*p1[i11];
        long o = (((long)b * Sn + s) * Cn + c) * HWn + hw;
        samp[o] = v;
        sw[o] = pack_hilo(v);
    }
}

// ---------------------------------------------------------------------------
__global__ void combine_k(const float* __restrict__ samp,
                          const float* __restrict__ wts,
                          float* __restrict__ res_i, float* __restrict__ outp)
{
    long idx = blockIdx.x * 256L + threadIdx.x;
    if (idx >= (long)Bn * HWn) return;
    int hw = (int)(idx % HWn);
    int b  = (int)(idx / HWn);

    float wv[Sn];
#pragma unroll
    for (int s = 0; s < Sn; s++) wv[s] = wts[((long)b * Sn + s) * HWn + hw];

    float o[3] = {0.f, 0.f, 0.f};
#pragma unroll
    for (int g = 0; g < 3; g++) {
#pragma unroll
        for (int c = 0; c < 3; c++) {
            float r = 0.f;
#pragma unroll
            for (int k = 0; k < 9; k++) {
                int s = g * 9 + k;
                r += samp[(((long)b * Sn + s) * Cn + c) * HWn + hw] * wv[s];
            }
            r *= 3.0f;
            res_i[(((long)b * 3 + g) * 3 + c) * HWn + hw] = r;
            o[c] += r;
        }
    }
#pragma unroll
    for (int c = 0; c < 3; c++)
        outp[((long)b * 3 + c) * HWn + hw] = o[c] * (1.0f / 3.0f);
}

// ---------------------------------------------------------------------------
extern "C" void kernel_launch(void* const* d_in, const int* in_sizes, int n_in,
                              void* d_out, int out_size)
{
    const float* data   = (const float*)d_in[0];
    const float* enc_w1 = (const float*)d_in[1];
    const float* enc_b1 = (const float*)d_in[2];
    const float* enc_w2 = (const float*)d_in[3];
    const float* enc_b2 = (const float*)d_in[4];
    const float* off_w  = (const float*)d_in[5];
    const float* off_b  = (const float*)d_in[6];
    const float* wc_w1  = (const float*)d_in[7];
    const float* wc_b1  = (const float*)d_in[8];
    const float* wc_w2  = (const float*)d_in[9];
    const float* wc_b2  = (const float*)d_in[10];
    const float* wc_w3  = (const float*)d_in[11];
    const float* wc_b3  = (const float*)d_in[12];
    float* out = (float*)d_out;

    u32 *dw, *f1w, *ftw, *spw, *h1w, *h2w;
    float *offs, *wt;
    uint2 *bh, *bl;
    cudaGetSymbolAddress((void**)&dw,  g_data_w);
    cudaGetSymbolAddress((void**)&f1w, g_f1_w);
    cudaGetSymbolAddress((void**)&ftw, g_feat_w);
    cudaGetSymbolAddress((void**)&spw, g_samp_w);
    cudaGetSymbolAddress((void**)&h1w, g_h1_w);
    cudaGetSymbolAddress((void**)&h2w, g_h2_w);
    cudaGetSymbolAddress((void**)&offs, g_off);
    cudaGetSymbolAddress((void**)&wt,  g_wt);
    cudaGetSymbolAddress((void**)&bh,  g_bfh);
    cudaGetSymbolAddress((void**)&bl,  g_bfl);
    dw += GUARD; f1w += GUARD; ftw += GUARD; spw += GUARD; h1w += GUARD; h2w += GUARD;

    float* res_i = out + RES_OFF;
    float* outp  = out + OUT_OFF;
    float* samp  = out + SAMP_OFF;

    // 1) split input data to interleaved fp16 hi|lo plane
    {
        long n = 4L * 15 * HWn;
        split_k<<<(unsigned)((n + 255) / 256), 256>>>(data, dw, n);
    }
    // 2) pack all weights (fragment order, hi+lo)
    packall_k<<<(95744 + 255) / 256, 256>>>(enc_w1, enc_w2, off_w,
                                            wc_w1, wc_w2, wc_w3, bh, bl);

    const int DSM_8_3 = 2 * A_BUFB + 4 * 128 * 8 * 8;   // 47872+32768 = 80640
    const int DSM_8_2 = 2 * A_BUFB + 2 * 128 * 8 * 8;   // 64256
    const int DSM_4_3 = 2 * A_BUFB + 4 * 128 * 4 * 8;   // 64256
    const int DSM_4_2 = 2 * A_BUFB + 2 * 128 * 4 * 8;   // 56064
    cudaFuncSetAttribute(convM_k<8,3>, cudaFuncAttributeMaxDynamicSharedMemorySize, DSM_8_3);
    cudaFuncSetAttribute(convM_k<8,2>, cudaFuncAttributeMaxDynamicSharedMemorySize, DSM_8_2);
    cudaFuncSetAttribute(convM_k<4,3>, cudaFuncAttributeMaxDynamicSharedMemorySize, DSM_4_3);
    cudaFuncSetAttribute(convM_k<4,2>, cudaFuncAttributeMaxDynamicSharedMemorySize, DSM_4_2);

    const unsigned GRID = 1024;

    // 3) f1 = relu(conv(data 15->64)), 3-term
    convM_k<8,3><<<GRID, 256, DSM_8_3>>>(dw, 15, nullptr, 0, nullptr,
        bh + 0*40960L, bl + 0*40960L, enc_b1, f1w, nullptr, 15, 64, 192, 8, 0, 1);
    // 4) feature = relu(conv(f1 64->128)), 3-term, two N slices
    convM_k<8,3><<<GRID, 256, DSM_8_3>>>(f1w, 64, nullptr, 0, nullptr,
        bh + 1*40960L, bl + 1*40960L, enc_b2, ftw, nullptr, 64, 128, 576, 16, 0, 1);
    convM_k<8,3><<<GRID, 256, DSM_8_3>>>(f1w, 64, nullptr, 0, nullptr,
        bh + 1*40960L, bl + 1*40960L, enc_b2, ftw, nullptr, 64, 128, 576, 16, 1, 1);
    // 5) offsets = conv(feature 128->81) fp32, 3-term, slices NT8 + NT4
    convM_k<8,3><<<GRID, 256, DSM_8_3>>>(ftw, 128, nullptr, 0, nullptr,
        bh + 2*40960L, bl + 2*40960L, off_b, nullptr, offs, 128, 81, 1152, 12, 0, 0);
    convM_k<4,3><<<GRID, 256, DSM_4_3>>>(ftw, 128, nullptr, 0, nullptr,
        bh + 2*40960L, bl + 2*40960L, off_b, nullptr, offs, 128, 81, 1152, 12, 1, 0);
    // 6) samples (fp32 to d_out + interleaved plane)
    {
        long n = (long)Bn * Sn * HWn;
        trilerp_k<<<(unsigned)((n + 255) / 256), 256>>>(data, offs, samp, spw);
    }
    // 7) h1 = relu(conv(concat(data15, feat128, samp81) 224->64)), 2-term
    convM_k<8,2><<<GRID, 256, DSM_8_2>>>(dw, 15, ftw, 128, spw,
        bh + 3*40960L, bl + 3*40960L, wc_b1, h1w, nullptr, 224, 64, 2048, 8, 0, 1);
    // 8) h2 = relu(conv(h1 64->64)), 2-term
    convM_k<8,2><<<GRID, 256, DSM_8_2>>>(h1w, 64, nullptr, 0, nullptr,
        bh + 4*40960L, bl + 4*40960L, wc_b2, h2w, nullptr, 64, 64, 576, 8, 0, 1);
    // 9) weights = conv(h2 64->27) fp32, 2-term
    convM_k<4,2><<<GRID, 256, DSM_4_2>>>(h2w, 64, nullptr, 0, nullptr,
        bh + 5*40960L, bl + 5*40960L, wc_b3, nullptr, wt, 64, 27, 576, 4, 0, 0);
    // 10) combine
    {
        long n = (long)Bn * HWn;
        combine_k<<<(unsigned)((n + 255) / 256), 256>>>(samp, wt, res_i, outp);
    }
}

// round 11
// speedup vs baseline: 1.9281x; 1.0779x over previous
#include <cuda_runtime.h>
#include <cuda_fp16.h>

#define Hd 256
#define Wd 256
#define HWn 65536
#define Bn 4
#define Dn 5
#define Cn 3
#define Sn 27

#define RES_OFF  0L
#define OUT_OFF  (4L*3*3*HWn)
#define SAMP_OFF (OUT_OFF + 4L*3*HWn)

typedef unsigned short u16;
typedef unsigned int u32;

#define GUARD 16   // u32 guard elements before/after each plane region

// ---------------- interleaved fp16 hi|lo planes (u32/elem, guarded) -------
__device__ __align__(16) u32 g_data_w[4L*15*HWn + 2*GUARD];
__device__ __align__(16) u32 g_f1_w[4L*64*HWn + 2*GUARD];
__device__ __align__(16) u32 g_feat_w[4L*128*HWn + 2*GUARD];
__device__ __align__(16) u32 g_samp_w[4L*81*HWn + 2*GUARD];
__device__ __align__(16) u32 g_h1_w[4L*64*HWn + 2*GUARD];
__device__ __align__(16) u32 g_h2_w[4L*64*HWn + 2*GUARD];
__device__ float g_off[4L*81*HWn];
__device__ float g_wt[4L*27*HWn];
__device__ uint4 g_bf[95744];     // fragment-ordered fp16 weights {bh0,bh1,bl0,bl1}

__device__ __forceinline__ u16 f16_hi(float v) {
    __half h = __float2half_rn(v);
    return *reinterpret_cast<u16*>(&h);
}
__device__ __forceinline__ float f16_f(u16 b) {
    __half h = *reinterpret_cast<__half*>(&b);
    return __half2float(h);
}
__device__ __forceinline__ u32 pack_hilo(float v) {
    u16 hv = f16_hi(v);
    u16 lv = f16_hi(v - f16_f(hv));
    return (u32)hv | ((u32)lv << 16);
}
__device__ __forceinline__ u32 smem_u32(const void* p) {
    u32 a;
    asm("{ .reg .u64 t; cvta.to.shared.u64 t, %1; cvt.u32.u64 %0, t; }" : "=r"(a) : "l"(p));
    return a;
}
__device__ __forceinline__ void cp16(u32 dst, const void* src) {
    asm volatile("cp.async.cg.shared.global [%0], [%1], 16;" :: "r"(dst), "l"(src));
}
#define CP_COMMIT() asm volatile("cp.async.commit_group;")

// ---------------------------------------------------------------------------
__global__ void split_k(const float* __restrict__ src, u32* __restrict__ dw, long n)
{
    long i = blockIdx.x * 256L + threadIdx.x;
    if (i >= n) return;
    dw[i] = pack_hilo(src[i]);
}

// ---------------------------------------------------------------------------
// pack ALL conv weights into mma B-fragment order, uint4 {bh0,bh1,bl0,bl1}.
// Fragment layout (verified R6-R10): element le = (q*NTt + ng)*32 + lane,
// g=lane>>2, t=lane&3; n = ng*8+g; kb = q*16+2t;
// pairs (kb,kb+1),(kb+8,kb+9).
// ---------------------------------------------------------------------------
__global__ void packall_k(const float* w0, const float* w1, const float* w2,
                          const float* w3, const float* w4, const float* w5,
                          uint4* __restrict__ bf)
{
    long e = blockIdx.x * 256L + threadIdx.x;
    if (e >= 95744) return;
    int ci; long base;
    if      (e < 3072)  { ci = 0; base = 0; }
    else if (e < 21504) { ci = 1; base = 3072; }
    else if (e < 49152) { ci = 2; base = 21504; }
    else if (e < 81920) { ci = 3; base = 49152; }
    else if (e < 91136) { ci = 4; base = 81920; }
    else                { ci = 5; base = 91136; }
    const float* wp = ci == 0 ? w0 : ci == 1 ? w1 : ci == 2 ? w2
                    : ci == 3 ? w3 : ci == 4 ? w4 : w5;
    const int COUTs[6] = {64, 128, 81, 64, 64, 27};
    const int Ks[6]    = {135, 576, 1152, 2016, 576, 576};
    const int NTts[6]  = {8, 16, 12, 8, 8, 4};
    int COUT = COUTs[ci], K = Ks[ci], NTt = NTts[ci];

    long le = e - base;
    int lane = (int)(le & 31);
    long r = le >> 5;
    int ng = (int)(r % NTt);
    int q  = (int)(r / NTt);
    int g = lane >> 2, t = lane & 3;
    int n = ng * 8 + g;
    int kb = q * 16 + 2 * t;

    float v[4];
    int kk[4] = {kb, kb + 1, kb + 8, kb + 9};
#pragma unroll
    for (int i = 0; i < 4; i++)
        v[i] = (n < COUT && kk[i] < K) ? wp[(long)n * K + kk[i]] : 0.f;

    u16 h[4], l[4];
#pragma unroll
    for (int i = 0; i < 4; i++) {
        h[i] = f16_hi(v[i]);
        l[i] = f16_hi(v[i] - f16_f(h[i]));
    }
    bf[e] = make_uint4((u32)h[0] | ((u32)h[1] << 16), (u32)h[2] | ((u32)h[3] << 16),
                       (u32)l[0] | ((u32)l[1] << 16), (u32)l[2] | ((u32)l[3] << 16));
}

// ---------------------------------------------------------------------------
__device__ __forceinline__ void mma16816(float d[4], const u32 a[4], u32 b0, u32 b1)
{
    asm volatile(
        "mma.sync.aligned.m16n8k16.row.col.f32.f16.f16.f32 "
        "{%0,%1,%2,%3}, {%4,%5,%6,%7}, {%8,%9}, {%0,%1,%2,%3};"
        : "+f"(d[0]), "+f"(d[1]), "+f"(d[2]), "+f"(d[3])
        : "r"(a[0]), "r"(a[1]), "r"(a[2]), "r"(a[3]), "r"(b0), "r"(b1));
}

// ---------------------------------------------------------------------------
// Implicit-GEMM 3x3 conv, M=256 (full image row), N = NT*8 at slice*64 offset.
// A: raw input rows (cin,kh) with 4-u32 halo each side, interleaved {hi,lo};
//    fragment offset for kernel column kw is kw + 3 (SMEM idx i <-> ww = i-4).
// B: fragment-ordered uint4 {bh0,bh1,bl0,bl1} -> one LDS.128 per (ks,nt).
// cp.async double-buffered; 2 barriers per chunk (fixup merged before sync).
// TERMS==2: D = Ah*Bh + Al*Bh.  TERMS==3: + Ah*Bl.
// ---------------------------------------------------------------------------
#define A_ROWS   22
#define A_PITCHW 272                         // u32 per raw row
#define A_BUFB   (A_ROWS*A_PITCHW*4)         // 23936 bytes per A buffer

template<int NT, int TERMS>
__global__ void __launch_bounds__(256, 2)
convM_k(const u32* __restrict__ s0, int c0,
        const u32* __restrict__ s1, int c1,
        const u32* __restrict__ s2,
        const uint4* __restrict__ bfrag,
        const float* __restrict__ bias,
        u32* __restrict__ dstw, float* __restrict__ dstf,
        int CIN, int COUT, int Kpad, int NTt, int slice, int relu)
{
    extern __shared__ char sm[];
    const u32 smbase = smem_u32(sm);
    const int BSZB = 128 * NT * 16;          // bytes per B buffer (uint4 frags)

    const int tid = threadIdx.x;
    const int wid = tid >> 5;
    const int lane = tid & 31;
    const int g = lane >> 2;
    const int t = lane & 3;
    const int b = blockIdx.x >> 8;
    const int h = blockIdx.x & 255;
    const int mb = wid * 16;

    const int c01 = c0 + c1;
    const int c2 = CIN - c01;
    const int nchunk = Kpad >> 6;

    float acc[2][NT][4];
#pragma unroll
    for (int mt = 0; mt < 2; mt++)
#pragma unroll
        for (int i = 0; i < NT; i++)
#pragma unroll
            for (int j = 0; j < 4; j++) acc[mt][i][j] = 0.f;

    // ---- fill one chunk's A raw rows + B fragments into buffer `buf` ----
    auto fill = [&](int kc, int buf) {
        const int K0 = kc * 64;
        const int T0 = (int)(((unsigned)K0 * 21846u) >> 16);
        const u32 abase = smbase + buf * A_BUFB;
        // A: 22 rows x 68 16B-chunks (u32 interleaved plane)
        for (int e = tid; e < A_ROWS * 68; e += 256) {
            int tt = e / 68;
            int j = e - tt * 68;
            int T = T0 + tt;
            int cin = (int)(((unsigned)T * 21846u) >> 16);
            int kh = T - cin * 3;
            int hh = h + kh - 1;
            u32 dst = abase + (u32)(tt * 1088 + j * 16);
            if (cin < CIN && (unsigned)hh < 256u) {
                const u32* sp;
                if (cin < c0)       sp = s0 + ((long)b * c0 + cin) * HWn;
                else if (cin < c01) sp = s1 + ((long)b * c1 + (cin - c0)) * HWn;
                else                sp = s2 + ((long)b * c2 + (cin - c01)) * HWn;
                cp16(dst, sp + (long)hh * 256 + j * 4 - 4);
            } else {
                asm volatile("st.shared.v4.b32 [%0], {%1,%1,%1,%1};" :: "r"(dst), "r"(0u));
            }
        }
        // B fragments: 128*NT uint4 per chunk
        const u32 bhb = smbase + 2 * A_BUFB + buf * BSZB;
        const int q0 = kc * 4;
        for (int e = tid; e < 128 * NT; e += 256) {
            int ks = e / (NT * 32);
            int r = e - ks * (NT * 32);
            long fo = ((long)(q0 + ks) * NTt + slice * 8) * 32 + r;
            cp16(bhb + (u32)e * 16, bfrag + fo);
        }
    };

    fill(0, 0);
    CP_COMMIT();

    for (int kc = 0; kc < nchunk; ++kc) {
        const int buf = kc & 1;
        if (kc + 1 < nchunk) {
            fill(kc + 1, buf ^ 1);
            CP_COMMIT();
            asm volatile("cp.async.wait_group 1;");
        } else {
            asm volatile("cp.async.wait_group 0;");
        }

        // edge fixups on cur buf (cp.asyncs for it are drained by wait_group):
        // zero halo cells ww=-1 (index 3) and ww=256 (index 260)
        u32* Aw = (u32*)(sm + buf * A_BUFB);
        if (tid < A_ROWS) {
            Aw[tid * A_PITCHW + 3] = 0;
            Aw[tid * A_PITCHW + 260] = 0;
        }
        __syncthreads();

        const uint4* Bf = (const uint4*)(sm + 2 * A_BUFB + buf * BSZB);
        const int K0 = kc * 64;
        const int T0 = (int)(((unsigned)K0 * 21846u) >> 16);

#pragma unroll
        for (int ks = 0; ks < 4; ks++) {
            int kg = K0 + ks * 16 + 2 * t;
            int Ta = (int)(((unsigned)kg * 21846u) >> 16);        int kwa = kg - Ta * 3;
            int Tb = (int)(((unsigned)(kg + 1) * 21846u) >> 16);  int kwb = kg + 1 - Tb * 3;
            int Tc = (int)(((unsigned)(kg + 8) * 21846u) >> 16);  int kwc = kg + 8 - Tc * 3;
            int Td = (int)(((unsigned)(kg + 9) * 21846u) >> 16);  int kwd = kg + 9 - Td * 3;
            int ra = (Ta - T0) * A_PITCHW + kwa + 3;
            int rb = (Tb - T0) * A_PITCHW + kwb + 3;
            int rc = (Tc - T0) * A_PITCHW + kwc + 3;
            int rd = (Td - T0) * A_PITCHW + kwd + 3;

            u32 ah[2][4], al[2][4];
#pragma unroll
            for (int mt = 0; mt < 2; mt++) {
                int m = mb + mt * 128 + g;
                u32 x0 = Aw[ra + m],     y0 = Aw[rb + m];
                u32 x1 = Aw[ra + m + 8], y1 = Aw[rb + m + 8];
                u32 x2 = Aw[rc + m],     y2 = Aw[rd + m];
                u32 x3 = Aw[rc + m + 8], y3 = Aw[rd + m + 8];
                ah[mt][0] = __byte_perm(x0, y0, 0x5410); al[mt][0] = __byte_perm(x0, y0, 0x7632);
                ah[mt][1] = __byte_perm(x1, y1, 0x5410); al[mt][1] = __byte_perm(x1, y1, 0x7632);
                ah[mt][2] = __byte_perm(x2, y2, 0x5410); al[mt][2] = __byte_perm(x2, y2, 0x7632);
                ah[mt][3] = __byte_perm(x3, y3, 0x5410); al[mt][3] = __byte_perm(x3, y3, 0x7632);
            }
            const uint4* Bp = Bf + ks * NT * 32 + lane;
#pragma unroll
            for (int nt = 0; nt < NT; nt++) {
                uint4 bv = Bp[nt * 32];
                mma16816(acc[0][nt], ah[0], bv.x, bv.y);
                mma16816(acc[0][nt], al[0], bv.x, bv.y);
                mma16816(acc[1][nt], ah[1], bv.x, bv.y);
                mma16816(acc[1][nt], al[1], bv.x, bv.y);
                if (TERMS == 3) {
                    mma16816(acc[0][nt], ah[0], bv.z, bv.w);
                    mma16816(acc[1][nt], ah[1], bv.z, bv.w);
                }
            }
        }
        __syncthreads();   // protect buf from next prefetch overwrite
    }

    // ---- epilogue ----
#pragma unroll
    for (int mt = 0; mt < 2; mt++)
#pragma unroll
        for (int nt = 0; nt < NT; nt++) {
            int n0 = slice * 64 + nt * 8 + t * 2;
#pragma unroll
            for (int i = 0; i < 4; i++) {
                int n = n0 + (i & 1);
                if (n >= COUT) continue;
                int m = mb + mt * 128 + g + ((i & 2) ? 8 : 0);
                float v = acc[mt][nt][i] + bias[n];
                if (relu) v = fmaxf(v, 0.f);
                long o = ((long)b * COUT + n) * HWn + (long)h * 256 + m;
                if (dstw) dstw[o] = pack_hilo(v);
                if (dstf) dstf[o] = v;
            }
        }
}

// ---------------------------------------------------------------------------
__global__ void trilerp_k(const float* __restrict__ data,
                          const float* __restrict__ off,
                          float* __restrict__ samp, u32* __restrict__ sw)
{
    long idx = blockIdx.x * 256L + threadIdx.x;
    if (idx >= (long)Bn * Sn * HWn) return;
    int hw = (int)(idx % HWn);
    int s  = (int)((idx / HWn) % Sn);
    int b  = (int)(idx / ((long)Sn * HWn));
    int h = hw >> 8, w = hw & 255;

    int kd = s / 9 - 1, kh = (s / 3) % 3 - 1, kw = s % 3 - 1;

    const float* ob = off + ((long)b * (Sn * 3) + s * 3) * HWn + hw;
    float pd = 2.0f + (float)kd + ob[0];
    float ph = (float)h + (float)kh + ob[HWn];
    float pw = (float)w + (float)kw + ob[2L * HWn];
    pd = fminf(fmaxf(pd, 0.f), (float)(Dn - 1));
    ph = fminf(fmaxf(ph, 0.f), (float)(Hd - 1));
    pw = fminf(fmaxf(pw, 0.f), (float)(Wd - 1));

    float d0f = floorf(pd), h0f = floorf(ph), w0f = floorf(pw);
    float fd = pd - d0f, fh = ph - h0f, fw = pw - w0f;
    int d0 = (int)d0f, h0 = (int)h0f, w0 = (int)w0f;
    int d1 = min(d0 + 1, Dn - 1), h1 = min(h0 + 1, Hd - 1), w1 = min(w0 + 1, Wd - 1);

    float gd0 = 1.f - fd, gh0 = 1.f - fh, gw0 = 1.f - fw;
    float w000 = gd0*gh0*gw0, w001 = gd0*gh0*fw, w010 = gd0*fh*gw0, w011 = gd0*fh*fw;
    float w100 = fd*gh0*gw0,  w101 = fd*gh0*fw,  w110 = fd*fh*gw0,  w111 = fd*fh*fw;

    long i00 = (long)h0 * Wd + w0, i01 = (long)h0 * Wd + w1;
    long i10 = (long)h1 * Wd + w0, i11 = (long)h1 * Wd + w1;

#pragma unroll
    for (int c = 0; c < Cn; c++) {
        const float* p0 = data + (((long)b * Dn + d0) * Cn + c) * HWn;
        const float* p1 = data + (((long)b * Dn + d1) * Cn + c) * HWn;
        float v = w000*p0[i00] + w001*p0[i01] + w010*p0[i10] + w011*p0[i11]
                + w100*p1[i00] + w101*p1[i01] + w110*p1[i10] + w111*p1[i11];
        long o = (((long)b * Sn + s) * Cn + c) * HWn + hw;
        samp[o] = v;
        sw[o] = pack_hilo(v);
    }
}

// ---------------------------------------------------------------------------
__global__ void combine_k(const float* __restrict__ samp,
                          const float* __restrict__ wts,
                          float* __restrict__ res_i, float* __restrict__ outp)
{
    long idx = blockIdx.x * 256L + threadIdx.x;
    if (idx >= (long)Bn * HWn) return;
    int hw = (int)(idx % HWn);
    int b  = (int)(idx / HWn);

    float wv[Sn];
#pragma unroll
    for (int s = 0; s < Sn; s++) wv[s] = wts[((long)b * Sn + s) * HWn + hw];

    float o[3] = {0.f, 0.f, 0.f};
#pragma unroll
    for (int g = 0; g < 3; g++) {
#pragma unroll
        for (int c = 0; c < 3; c++) {
            float r = 0.f;
#pragma unroll
            for (int k = 0; k < 9; k++) {
                int s = g * 9 + k;
                r += samp[(((long)b * Sn + s) * Cn + c) * HWn + hw] * wv[s];
            }
            r *= 3.0f;
            res_i[(((long)b * 3 + g) * 3 + c) * HWn + hw] = r;
            o[c] += r;
        }
    }
#pragma unroll
    for (int c = 0; c < 3; c++)
        outp[((long)b * 3 + c) * HWn + hw] = o[c] * (1.0f / 3.0f);
}

// ---------------------------------------------------------------------------
extern "C" void kernel_launch(void* const* d_in, const int* in_sizes, int n_in,
                              void* d_out, int out_size)
{
    const float* data   = (const float*)d_in[0];
    const float* enc_w1 = (const float*)d_in[1];
    const float* enc_b1 = (const float*)d_in[2];
    const float* enc_w2 = (const float*)d_in[3];
    const float* enc_b2 = (const float*)d_in[4];
    const float* off_w  = (const float*)d_in[5];
    const float* off_b  = (const float*)d_in[6];
    const float* wc_w1  = (const float*)d_in[7];
    const float* wc_b1  = (const float*)d_in[8];
    const float* wc_w2  = (const float*)d_in[9];
    const float* wc_b2  = (const float*)d_in[10];
    const float* wc_w3  = (const float*)d_in[11];
    const float* wc_b3  = (const float*)d_in[12];
    float* out = (float*)d_out;

    u32 *dw, *f1w, *ftw, *spw, *h1w, *h2w;
    float *offs, *wt;
    uint4* bf;
    cudaGetSymbolAddress((void**)&dw,  g_data_w);
    cudaGetSymbolAddress((void**)&f1w, g_f1_w);
    cudaGetSymbolAddress((void**)&ftw, g_feat_w);
    cudaGetSymbolAddress((void**)&spw, g_samp_w);
    cudaGetSymbolAddress((void**)&h1w, g_h1_w);
    cudaGetSymbolAddress((void**)&h2w, g_h2_w);
    cudaGetSymbolAddress((void**)&offs, g_off);
    cudaGetSymbolAddress((void**)&wt,  g_wt);
    cudaGetSymbolAddress((void**)&bf,  g_bf);
    dw += GUARD; f1w += GUARD; ftw += GUARD; spw += GUARD; h1w += GUARD; h2w += GUARD;

    float* res_i = out + RES_OFF;
    float* outp  = out + OUT_OFF;
    float* samp  = out + SAMP_OFF;

    // 1) split input data to interleaved fp16 hi|lo plane
    {
        long n = 4L * 15 * HWn;
        split_k<<<(unsigned)((n + 255) / 256), 256>>>(data, dw, n);
    }
    // 2) pack all weights (fragment order, uint4 hi|lo)
    packall_k<<<(95744 + 255) / 256, 256>>>(enc_w1, enc_w2, off_w,
                                            wc_w1, wc_w2, wc_w3, bf);

    const int DSM_8 = 2 * A_BUFB + 2 * 128 * 8 * 16;   // 47872+32768 = 80640
    const int DSM_4 = 2 * A_BUFB + 2 * 128 * 4 * 16;   // 47872+16384 = 64256
    cudaFuncSetAttribute(convM_k<8,3>, cudaFuncAttributeMaxDynamicSharedMemorySize, DSM_8);
    cudaFuncSetAttribute(convM_k<8,2>, cudaFuncAttributeMaxDynamicSharedMemorySize, DSM_8);
    cudaFuncSetAttribute(convM_k<4,3>, cudaFuncAttributeMaxDynamicSharedMemorySize, DSM_4);
    cudaFuncSetAttribute(convM_k<4,2>, cudaFuncAttributeMaxDynamicSharedMemorySize, DSM_4);

    const unsigned GRID = 1024;

    // 3) f1 = relu(conv(data 15->64)), 3-term
    convM_k<8,3><<<GRID, 256, DSM_8>>>(dw, 15, nullptr, 0, nullptr,
        bf + 0L, enc_b1, f1w, nullptr, 15, 64, 192, 8, 0, 1);
    // 4) feature = relu(conv(f1 64->128)), 3-term, two N slices
    convM_k<8,3><<<GRID, 256, DSM_8>>>(f1w, 64, nullptr, 0, nullptr,
        bf + 3072L, enc_b2, ftw, nullptr, 64, 128, 576, 16, 0, 1);
    convM_k<8,3><<<GRID, 256, DSM_8>>>(f1w, 64, nullptr, 0, nullptr,
        bf + 3072L, enc_b2, ftw, nullptr, 64, 128, 576, 16, 1, 1);
    // 5) offsets = conv(feature 128->81) fp32, 3-term, slices NT8 + NT4
    convM_k<8,3><<<GRID, 256, DSM_8>>>(ftw, 128, nullptr, 0, nullptr,
        bf + 21504L, off_b, nullptr, offs, 128, 81, 1152, 12, 0, 0);
    convM_k<4,3><<<GRID, 256, DSM_4>>>(ftw, 128, nullptr, 0, nullptr,
        bf + 21504L, off_b, nullptr, offs, 128, 81, 1152, 12, 1, 0);
    // 6) samples (fp32 to d_out + interleaved plane)
    {
        long n = (long)Bn * Sn * HWn;
        trilerp_k<<<(unsigned)((n + 255) / 256), 256>>>(data, offs, samp, spw);
    }
    // 7) h1 = relu(conv(concat(data15, feat128, samp81) 224->64)), 2-term
    convM_k<8,2><<<GRID, 256, DSM_8>>>(dw, 15, ftw, 128, spw,
        bf + 49152L, wc_b1, h1w, nullptr, 224, 64, 2048, 8, 0, 1);
    // 8) h2 = relu(conv(h1 64->64)), 2-term
    convM_k<8,2><<<GRID, 256, DSM_8>>>(h1w, 64, nullptr, 0, nullptr,
        bf + 81920L, wc_b2, h2w, nullptr, 64, 64, 576, 8, 0, 1);
    // 9) weights = conv(h2 64->27) fp32, 2-term
    convM_k<4,2><<<GRID, 256, DSM_4>>>(h2w, 64, nullptr, 0, nullptr,
        bf + 91136L, wc_b3, nullptr, wt, 64, 27, 576, 4, 0, 0);
    // 10) combine
    {
        long n = (long)Bn * HWn;
        combine_k<<<(unsigned)((n + 255) / 256), 256>>>(samp, wt, res_i, outp);
    }
}

// round 12
// speedup vs baseline: 1.9459x; 1.0093x over previous
#include <cuda_runtime.h>
#include <cuda_fp16.h>

#define Hd 256
#define Wd 256
#define HWn 65536
#define Bn 4
#define Dn 5
#define Cn 3
#define Sn 27

#define RES_OFF  0L
#define OUT_OFF  (4L*3*3*HWn)
#define SAMP_OFF (OUT_OFF + 4L*3*HWn)

typedef unsigned short u16;
typedef unsigned int u32;

#define GUARD 16   // u32 guard elements before/after each plane region

// ---------------- interleaved fp16 hi|lo planes (u32/elem, guarded) -------
__device__ __align__(16) u32 g_data_w[4L*15*HWn + 2*GUARD];
__device__ __align__(16) u32 g_f1_w[4L*64*HWn + 2*GUARD];
__device__ __align__(16) u32 g_feat_w[4L*128*HWn + 2*GUARD];
__device__ __align__(16) u32 g_samp_w[4L*81*HWn + 2*GUARD];
__device__ __align__(16) u32 g_h1_w[4L*64*HWn + 2*GUARD];
__device__ __align__(16) u32 g_h2_w[4L*64*HWn + 2*GUARD];
__device__ float g_off[4L*81*HWn];
__device__ float g_wt[4L*27*HWn];
__device__ uint4 g_bf[95744];     // fragment-ordered fp16 weights {bh0,bh1,bl0,bl1}

__device__ __forceinline__ u16 f16_hi(float v) {
    __half h = __float2half_rn(v);
    return *reinterpret_cast<u16*>(&h);
}
__device__ __forceinline__ float f16_f(u16 b) {
    __half h = *reinterpret_cast<__half*>(&b);
    return __half2float(h);
}
__device__ __forceinline__ u32 pack_hilo(float v) {
    u16 hv = f16_hi(v);
    u16 lv = f16_hi(v - f16_f(hv));
    return (u32)hv | ((u32)lv << 16);
}
__device__ __forceinline__ u32 smem_u32(const void* p) {
    u32 a;
    asm("{ .reg .u64 t; cvta.to.shared.u64 t, %1; cvt.u32.u64 %0, t; }" : "=r"(a) : "l"(p));
    return a;
}
__device__ __forceinline__ void cp16(u32 dst, const void* src) {
    asm volatile("cp.async.cg.shared.global [%0], [%1], 16;" :: "r"(dst), "l"(src));
}
#define CP_COMMIT() asm volatile("cp.async.commit_group;")

// ---------------------------------------------------------------------------
__global__ void split_k(const float* __restrict__ src, u32* __restrict__ dw, long n)
{
    long i = blockIdx.x * 256L + threadIdx.x;
    if (i >= n) return;
    dw[i] = pack_hilo(src[i]);
}

// ---------------------------------------------------------------------------
// pack ALL conv weights into mma B-fragment order, uint4 {bh0,bh1,bl0,bl1}.
// Fragment layout (verified R6-R11): element le = (q*NTt + ng)*32 + lane,
// g=lane>>2, t=lane&3; n = ng*8+g; kb = q*16+2t; pairs (kb,kb+1),(kb+8,kb+9).
// ---------------------------------------------------------------------------
__global__ void packall_k(const float* w0, const float* w1, const float* w2,
                          const float* w3, const float* w4, const float* w5,
                          uint4* __restrict__ bf)
{
    long e = blockIdx.x * 256L + threadIdx.x;
    if (e >= 95744) return;
    int ci; long base;
    if      (e < 3072)  { ci = 0; base = 0; }
    else if (e < 21504) { ci = 1; base = 3072; }
    else if (e < 49152) { ci = 2; base = 21504; }
    else if (e < 81920) { ci = 3; base = 49152; }
    else if (e < 91136) { ci = 4; base = 81920; }
    else                { ci = 5; base = 91136; }
    const float* wp = ci == 0 ? w0 : ci == 1 ? w1 : ci == 2 ? w2
                    : ci == 3 ? w3 : ci == 4 ? w4 : w5;
    const int COUTs[6] = {64, 128, 81, 64, 64, 27};
    const int Ks[6]    = {135, 576, 1152, 2016, 576, 576};
    const int NTts[6]  = {8, 16, 12, 8, 8, 4};
    int COUT = COUTs[ci], K = Ks[ci], NTt = NTts[ci];

    long le = e - base;
    int lane = (int)(le & 31);
    long r = le >> 5;
    int ng = (int)(r % NTt);
    int q  = (int)(r / NTt);
    int g = lane >> 2, t = lane & 3;
    int n = ng * 8 + g;
    int kb = q * 16 + 2 * t;

    float v[4];
    int kk[4] = {kb, kb + 1, kb + 8, kb + 9};
#pragma unroll
    for (int i = 0; i < 4; i++)
        v[i] = (n < COUT && kk[i] < K) ? wp[(long)n * K + kk[i]] : 0.f;

    u16 h[4], l[4];
#pragma unroll
    for (int i = 0; i < 4; i++) {
        h[i] = f16_hi(v[i]);
        l[i] = f16_hi(v[i] - f16_f(h[i]));
    }
    bf[e] = make_uint4((u32)h[0] | ((u32)h[1] << 16), (u32)h[2] | ((u32)h[3] << 16),
                       (u32)l[0] | ((u32)l[1] << 16), (u32)l[2] | ((u32)l[3] << 16));
}

// ---------------------------------------------------------------------------
__device__ __forceinline__ void mma16816(float d[4], const u32 a[4], u32 b0, u32 b1)
{
    asm volatile(
        "mma.sync.aligned.m16n8k16.row.col.f32.f16.f16.f32 "
        "{%0,%1,%2,%3}, {%4,%5,%6,%7}, {%8,%9}, {%0,%1,%2,%3};"
        : "+f"(d[0]), "+f"(d[1]), "+f"(d[2]), "+f"(d[3])
        : "r"(a[0]), "r"(a[1]), "r"(a[2]), "r"(a[3]), "r"(b0), "r"(b1));
}

// ---------------------------------------------------------------------------
// Implicit-GEMM 3x3 conv, M=256 (full image row).
// N slice: nbase = blockIdx.y * NT*8 (gridDim.y slices per launch).
// A: raw input rows (cin,kh) with 4-u32 halo each side, interleaved {hi,lo};
//    fragment offset for kernel column kw is kw + 3 (SMEM idx i <-> ww = i-4).
// B: fragment-ordered uint4 {bh0,bh1,bl0,bl1} -> one LDS.128 per (ks,nt).
// cp.async double-buffered; 2 barriers per chunk.
// TERMS==2: D = Ah*Bh + Al*Bh.  TERMS==3: + Ah*Bl.
// ---------------------------------------------------------------------------
#define A_ROWS   22
#define A_PITCHW 272                         // u32 per raw row
#define A_BUFB   (A_ROWS*A_PITCHW*4)         // 23936 bytes per A buffer

template<int NT, int TERMS>
__global__ void __launch_bounds__(256, 2)
convM_k(const u32* __restrict__ s0, int c0,
        const u32* __restrict__ s1, int c1,
        const u32* __restrict__ s2,
        const uint4* __restrict__ bfrag,
        const float* __restrict__ bias,
        u32* __restrict__ dstw, float* __restrict__ dstf,
        int CIN, int COUT, int Kpad, int NTt, int relu)
{
    extern __shared__ char sm[];
    const u32 smbase = smem_u32(sm);
    const int BSZB = 128 * NT * 16;          // bytes per B buffer (uint4 frags)

    const int tid = threadIdx.x;
    const int wid = tid >> 5;
    const int lane = tid & 31;
    const int g = lane >> 2;
    const int t = lane & 3;
    const int b = blockIdx.x >> 8;
    const int h = blockIdx.x & 255;
    const int nbase = blockIdx.y * (NT * 8);
    const int ngbase = blockIdx.y * NT;
    const int mb = wid * 16;

    const int c01 = c0 + c1;
    const int c2 = CIN - c01;
    const int nchunk = Kpad >> 6;

    float acc[2][NT][4];
#pragma unroll
    for (int mt = 0; mt < 2; mt++)
#pragma unroll
        for (int i = 0; i < NT; i++)
#pragma unroll
            for (int j = 0; j < 4; j++) acc[mt][i][j] = 0.f;

    // ---- fill one chunk's A raw rows + B fragments into buffer `buf` ----
    auto fill = [&](int kc, int buf) {
        const int K0 = kc * 64;
        const int T0 = (int)(((unsigned)K0 * 21846u) >> 16);
        const u32 abase = smbase + buf * A_BUFB;
        // A: 22 rows x 68 16B-chunks (u32 interleaved plane)
        for (int e = tid; e < A_ROWS * 68; e += 256) {
            int tt = e / 68;
            int j = e - tt * 68;
            int T = T0 + tt;
            int cin = (int)(((unsigned)T * 21846u) >> 16);
            int kh = T - cin * 3;
            int hh = h + kh - 1;
            u32 dst = abase + (u32)(tt * 1088 + j * 16);
            if (cin < CIN && (unsigned)hh < 256u) {
                const u32* sp;
                if (cin < c0)       sp = s0 + ((long)b * c0 + cin) * HWn;
                else if (cin < c01) sp = s1 + ((long)b * c1 + (cin - c0)) * HWn;
                else                sp = s2 + ((long)b * c2 + (cin - c01)) * HWn;
                cp16(dst, sp + (long)hh * 256 + j * 4 - 4);
            } else {
                asm volatile("st.shared.v4.b32 [%0], {%1,%1,%1,%1};" :: "r"(dst), "r"(0u));
            }
        }
        // B fragments: 128*NT uint4 per chunk
        const u32 bhb = smbase + 2 * A_BUFB + buf * BSZB;
        const int q0 = kc * 4;
        for (int e = tid; e < 128 * NT; e += 256) {
            int ks = e / (NT * 32);
            int r = e - ks * (NT * 32);
            long fo = ((long)(q0 + ks) * NTt + ngbase) * 32 + r;
            cp16(bhb + (u32)e * 16, bfrag + fo);
        }
    };

    fill(0, 0);
    CP_COMMIT();

    for (int kc = 0; kc < nchunk; ++kc) {
        const int buf = kc & 1;
        if (kc + 1 < nchunk) {
            fill(kc + 1, buf ^ 1);
            CP_COMMIT();
            asm volatile("cp.async.wait_group 1;");
        } else {
            asm volatile("cp.async.wait_group 0;");
        }

        // edge fixups on cur buf (cp.asyncs for it are drained by wait_group):
        // zero halo cells ww=-1 (index 3) and ww=256 (index 260)
        u32* Aw = (u32*)(sm + buf * A_BUFB);
        if (tid < A_ROWS) {
            Aw[tid * A_PITCHW + 3] = 0;
            Aw[tid * A_PITCHW + 260] = 0;
        }
        __syncthreads();

        const uint4* Bf = (const uint4*)(sm + 2 * A_BUFB + buf * BSZB);
        const int K0 = kc * 64;
        const int T0 = (int)(((unsigned)K0 * 21846u) >> 16);

#pragma unroll
        for (int ks = 0; ks < 4; ks++) {
            int kg = K0 + ks * 16 + 2 * t;
            int Ta = (int)(((unsigned)kg * 21846u) >> 16);        int kwa = kg - Ta * 3;
            int Tb = (int)(((unsigned)(kg + 1) * 21846u) >> 16);  int kwb = kg + 1 - Tb * 3;
            int Tc = (int)(((unsigned)(kg + 8) * 21846u) >> 16);  int kwc = kg + 8 - Tc * 3;
            int Td = (int)(((unsigned)(kg + 9) * 21846u) >> 16);  int kwd = kg + 9 - Td * 3;
            int ra = (Ta - T0) * A_PITCHW + kwa + 3;
            int rb = (Tb - T0) * A_PITCHW + kwb + 3;
            int rc = (Tc - T0) * A_PITCHW + kwc + 3;
            int rd = (Td - T0) * A_PITCHW + kwd + 3;

            u32 ah[2][4], al[2][4];
#pragma unroll
            for (int mt = 0; mt < 2; mt++) {
                int m = mb + mt * 128 + g;
                u32 x0 = Aw[ra + m],     y0 = Aw[rb + m];
                u32 x1 = Aw[ra + m + 8], y1 = Aw[rb + m + 8];
                u32 x2 = Aw[rc + m],     y2 = Aw[rd + m];
                u32 x3 = Aw[rc + m + 8], y3 = Aw[rd + m + 8];
                ah[mt][0] = __byte_perm(x0, y0, 0x5410); al[mt][0] = __byte_perm(x0, y0, 0x7632);
                ah[mt][1] = __byte_perm(x1, y1, 0x5410); al[mt][1] = __byte_perm(x1, y1, 0x7632);
                ah[mt][2] = __byte_perm(x2, y2, 0x5410); al[mt][2] = __byte_perm(x2, y2, 0x7632);
                ah[mt][3] = __byte_perm(x3, y3, 0x5410); al[mt][3] = __byte_perm(x3, y3, 0x7632);
            }
            const uint4* Bp = Bf + ks * NT * 32 + lane;
#pragma unroll
            for (int nt = 0; nt < NT; nt++) {
                uint4 bv = Bp[nt * 32];
                mma16816(acc[0][nt], ah[0], bv.x, bv.y);
                mma16816(acc[0][nt], al[0], bv.x, bv.y);
                mma16816(acc[1][nt], ah[1], bv.x, bv.y);
                mma16816(acc[1][nt], al[1], bv.x, bv.y);
                if (TERMS == 3) {
                    mma16816(acc[0][nt], ah[0], bv.z, bv.w);
                    mma16816(acc[1][nt], ah[1], bv.z, bv.w);
                }
            }
        }
        __syncthreads();   // protect buf from next prefetch overwrite
    }

    // ---- epilogue ----
#pragma unroll
    for (int mt = 0; mt < 2; mt++)
#pragma unroll
        for (int nt = 0; nt < NT; nt++) {
            int n0 = nbase + nt * 8 + t * 2;
#pragma unroll
            for (int i = 0; i < 4; i++) {
                int n = n0 + (i & 1);
                if (n >= COUT) continue;
                int m = mb + mt * 128 + g + ((i & 2) ? 8 : 0);
                float v = acc[mt][nt][i] + bias[n];
                if (relu) v = fmaxf(v, 0.f);
                long o = ((long)b * COUT + n) * HWn + (long)h * 256 + m;
                if (dstw) dstw[o] = pack_hilo(v);
                if (dstf) dstf[o] = v;
            }
        }
}

// ---------------------------------------------------------------------------
__global__ void trilerp_k(const float* __restrict__ data,
                          const float* __restrict__ off,
                          float* __restrict__ samp, u32* __restrict__ sw)
{
    long idx = blockIdx.x * 256L + threadIdx.x;
    if (idx >= (long)Bn * Sn * HWn) return;
    int hw = (int)(idx % HWn);
    int s  = (int)((idx / HWn) % Sn);
    int b  = (int)(idx / ((long)Sn * HWn));
    int h = hw >> 8, w = hw & 255;

    int kd = s / 9 - 1, kh = (s / 3) % 3 - 1, kw = s % 3 - 1;

    const float* ob = off + ((long)b * (Sn * 3) + s * 3) * HWn + hw;
    float pd = 2.0f + (float)kd + ob[0];
    float ph = (float)h + (float)kh + ob[HWn];
    float pw = (float)w + (float)kw + ob[2L * HWn];
    pd = fminf(fmaxf(pd, 0.f), (float)(Dn - 1));
    ph = fminf(fmaxf(ph, 0.f), (float)(Hd - 1));
    pw = fminf(fmaxf(pw, 0.f), (float)(Wd - 1));

    float d0f = floorf(pd), h0f = floorf(ph), w0f = floorf(pw);
    float fd = pd - d0f, fh = ph - h0f, fw = pw - w0f;
    int d0 = (int)d0f, h0 = (int)h0f, w0 = (int)w0f;
    int d1 = min(d0 + 1, Dn - 1), h1 = min(h0 + 1, Hd - 1), w1 = min(w0 + 1, Wd - 1);

    float gd0 = 1.f - fd, gh0 = 1.f - fh, gw0 = 1.f - fw;
    float w000 = gd0*gh0*gw0, w001 = gd0*gh0*fw, w010 = gd0*fh*gw0, w011 = gd0*fh*fw;
    float w100 = fd*gh0*gw0,  w101 = fd*gh0*fw,  w110 = fd*fh*gw0,  w111 = fd*fh*fw;

    long i00 = (long)h0 * Wd + w0, i01 = (long)h0 * Wd + w1;
    long i10 = (long)h1 * Wd + w0, i11 = (long)h1 * Wd + w1;

#pragma unroll
    for (int c = 0; c < Cn; c++) {
        const float* p0 = data + (((long)b * Dn + d0) * Cn + c) * HWn;
        const float* p1 = data + (((long)b * Dn + d1) * Cn + c) * HWn;
        float v = w000*p0[i00] + w001*p0[i01] + w010*p0[i10] + w011*p0[i11]
                + w100*p1[i00] + w101*p1[i01] + w110*p1[i10] + w111*p1[i11];
        long o = (((long)b * Sn + s) * Cn + c) * HWn + hw;
        samp[o] = v;
        sw[o] = pack_hilo(v);
    }
}

// ---------------------------------------------------------------------------
__global__ void combine_k(const float* __restrict__ samp,
                          const float* __restrict__ wts,
                          float* __restrict__ res_i, float* __restrict__ outp)
{
    long idx = blockIdx.x * 256L + threadIdx.x;
    if (idx >= (long)Bn * HWn) return;
    int hw = (int)(idx % HWn);
    int b  = (int)(idx / HWn);

    float wv[Sn];
#pragma unroll
    for (int s = 0; s < Sn; s++) wv[s] = wts[((long)b * Sn + s) * HWn + hw];

    float o[3] = {0.f, 0.f, 0.f};
#pragma unroll
    for (int g = 0; g < 3; g++) {
#pragma unroll
        for (int c = 0; c < 3; c++) {
            float r = 0.f;
#pragma unroll
            for (int k = 0; k < 9; k++) {
                int s = g * 9 + k;
                r += samp[(((long)b * Sn + s) * Cn + c) * HWn + hw] * wv[s];
            }
            r *= 3.0f;
            res_i[(((long)b * 3 + g) * 3 + c) * HWn + hw] = r;
            o[c] += r;
        }
    }
#pragma unroll
    for (int c = 0; c < 3; c++)
        outp[((long)b * 3 + c) * HWn + hw] = o[c] * (1.0f / 3.0f);
}

// ---------------------------------------------------------------------------
extern "C" void kernel_launch(void* const* d_in, const int* in_sizes, int n_in,
                              void* d_out, int out_size)
{
    const float* data   = (const float*)d_in[0];
    const float* enc_w1 = (const float*)d_in[1];
    const float* enc_b1 = (const float*)d_in[2];
    const float* enc_w2 = (const float*)d_in[3];
    const float* enc_b2 = (const float*)d_in[4];
    const float* off_w  = (const float*)d_in[5];
    const float* off_b  = (const float*)d_in[6];
    const float* wc_w1  = (const float*)d_in[7];
    const float* wc_b1  = (const float*)d_in[8];
    const float* wc_w2  = (const float*)d_in[9];
    const float* wc_b2  = (const float*)d_in[10];
    const float* wc_w3  = (const float*)d_in[11];
    const float* wc_b3  = (const float*)d_in[12];
    float* out = (float*)d_out;

    u32 *dw, *f1w, *ftw, *spw, *h1w, *h2w;
    float *offs, *wt;
    uint4* bf;
    cudaGetSymbolAddress((void**)&dw,  g_data_w);
    cudaGetSymbolAddress((void**)&f1w, g_f1_w);
    cudaGetSymbolAddress((void**)&ftw, g_feat_w);
    cudaGetSymbolAddress((void**)&spw, g_samp_w);
    cudaGetSymbolAddress((void**)&h1w, g_h1_w);
    cudaGetSymbolAddress((void**)&h2w, g_h2_w);
    cudaGetSymbolAddress((void**)&offs, g_off);
    cudaGetSymbolAddress((void**)&wt,  g_wt);
    cudaGetSymbolAddress((void**)&bf,  g_bf);
    dw += GUARD; f1w += GUARD; ftw += GUARD; spw += GUARD; h1w += GUARD; h2w += GUARD;

    float* res_i = out + RES_OFF;
    float* outp  = out + OUT_OFF;
    float* samp  = out + SAMP_OFF;

    // 1) split input data to interleaved fp16 hi|lo plane
    {
        long n = 4L * 15 * HWn;
        split_k<<<(unsigned)((n + 255) / 256), 256>>>(data, dw, n);
    }
    // 2) pack all weights (fragment order, uint4 hi|lo)
    packall_k<<<(95744 + 255) / 256, 256>>>(enc_w1, enc_w2, off_w,
                                            wc_w1, wc_w2, wc_w3, bf);

    const int DSM_8 = 2 * A_BUFB + 2 * 128 * 8 * 16;   // 80640
    const int DSM_4 = 2 * A_BUFB + 2 * 128 * 4 * 16;   // 64256
    cudaFuncSetAttribute(convM_k<8,3>, cudaFuncAttributeMaxDynamicSharedMemorySize, DSM_8);
    cudaFuncSetAttribute(convM_k<8,2>, cudaFuncAttributeMaxDynamicSharedMemorySize, DSM_8);
    cudaFuncSetAttribute(convM_k<4,2>, cudaFuncAttributeMaxDynamicSharedMemorySize, DSM_4);

    // 3) f1 = relu(conv(data 15->64)), 3-term
    convM_k<8,3><<<dim3(1024,1), 256, DSM_8>>>(dw, 15, nullptr, 0, nullptr,
        bf + 0L, enc_b1, f1w, nullptr, 15, 64, 192, 8, 1);
    // 4) feature = relu(conv(f1 64->128)), 3-term, 2 N-slices in one launch
    convM_k<8,3><<<dim3(1024,2), 256, DSM_8>>>(f1w, 64, nullptr, 0, nullptr,
        bf + 3072L, enc_b2, ftw, nullptr, 64, 128, 576, 16, 1);
    // 5) offsets = conv(feature 128->81) fp32, 2-term, 3 NT4-slices in one launch
    convM_k<4,2><<<dim3(1024,3), 256, DSM_4>>>(ftw, 128, nullptr, 0, nullptr,
        bf + 21504L, off_b, nullptr, offs, 128, 81, 1152, 12, 0);
    // 6) samples (fp32 to d_out + interleaved plane)
    {
        long n = (long)Bn * Sn * HWn;
        trilerp_k<<<(unsigned)((n + 255) / 256), 256>>>(data, offs, samp, spw);
    }
    // 7) h1 = relu(conv(concat(data15, feat128, samp81) 224->64)), 2-term
    convM_k<8,2><<<dim3(1024,1), 256, DSM_8>>>(dw, 15, ftw, 128, spw,
        bf + 49152L, wc_b1, h1w, nullptr, 224, 64, 2048, 8, 1);
    // 8) h2 = relu(conv(h1 64->64)), 2-term
    convM_k<8,2><<<dim3(1024,1), 256, DSM_8>>>(h1w, 64, nullptr, 0, nullptr,
        bf + 81920L, wc_b2, h2w, nullptr, 64, 64, 576, 8, 1);
    // 9) weights = conv(h2 64->27) fp32, 2-term
    convM_k<4,2><<<dim3(1024,1), 256, DSM_4>>>(h2w, 64, nullptr, 0, nullptr,
        bf + 91136L, wc_b3, nullptr, wt, 64, 27, 576, 4, 0);
    // 10) combine
    {
        long n = (long)Bn * HWn;
        combine_k<<<(unsigned)((n + 255) / 256), 256>>>(samp, wt, res_i, outp);
    }
}